// round 8
// baseline (speedup 1.0000x reference)
#include <cuda_runtime.h>
#include <cstdint>

#define T_STEPS 1024
#define B_SZ    32
#define I_SZ    512
#define H_SZ    512
#define G4      2048                 // 4*H
#define TBH     (T_STEPS * B_SZ * H_SZ)
#define BH      (B_SZ * H_SZ)
#define NG      4                    // independent batch groups (8 batches each)
#define NC      32                   // CTAs per group

typedef unsigned long long ull;

// ---------------- device scratch (no allocation allowed) ----------------
__device__ float g_gates[(size_t)T_STEPS * B_SZ * G4];   // [t][b][p], p = 4j+g
__device__ float g_wih_p[G4 * I_SZ];                     // packed W_ih (p = 4j+g)
__device__ float g_whh_sw[NC * 64 * H_SZ];               // per-CTA swizzled W_hh (LDS-order)
__device__ float g_bias_p[G4];                           // b_ih + b_hh, packed
__device__ float g_hbufT[NG * 2 * 8 * H_SZ];             // [grp][phase][j][b8] transposed h
__device__ unsigned g_cnt[NG * 32];                      // per-group arrival counters (padded)
__device__ unsigned g_genv[NG * NC * 32];                // per-CTA generation lines (128B apart)

// ---------------- packed f32x2 helpers ----------------
__device__ __forceinline__ void ffma2(ull &d, ull a, ull b) {
    asm("fma.rn.f32x2 %0, %1, %2, %3;" : "=l"(d) : "l"(a), "l"(b), "l"(d));
}
__device__ __forceinline__ void fadd2(ull &d, ull a) {
    asm("add.rn.f32x2 %0, %1, %2;" : "=l"(d) : "l"(d), "l"(a));
}
__device__ __forceinline__ ull pack2(float x) {
    ull r; asm("mov.b64 %0, {%1, %1};" : "=l"(r) : "f"(x)); return r;
}
__device__ __forceinline__ float2 unpack2(ull v) {
    float2 r; asm("mov.b64 {%0, %1}, %2;" : "=f"(r.x), "=f"(r.y) : "l"(v)); return r;
}
__device__ __forceinline__ unsigned ld_acq(const unsigned* p) {
    unsigned v; asm volatile("ld.acquire.gpu.global.u32 %0, [%1];" : "=r"(v) : "l"(p) : "memory");
    return v;
}
__device__ __forceinline__ void st_rel(unsigned* p, unsigned v) {
    asm volatile("st.release.gpu.global.u32 [%0], %1;" :: "l"(p), "r"(v) : "memory");
}

__device__ __forceinline__ float sigf(float x) {
    return __fdividef(1.f, 1.f + __expf(-x));
}
__device__ __forceinline__ float tanh_fast(float x) {
    float ax = fabsf(x);
    float e  = __expf(-2.f * ax);
    float r  = __fdividef(1.f - e, 1.f + e);
    return copysignf(r, x);
}

// ---------------- prep: pack/swizzle weights, transpose h0, reset sync ----------------
__global__ void prep_kernel(const float* __restrict__ Wih, const float* __restrict__ Whh,
                            const float* __restrict__ bih, const float* __restrict__ bhh,
                            const float* __restrict__ h0) {
    int p = blockIdx.x;                     // packed row p = 4j + g
    int g = p & 3, j = p >> 2;
    int orig = g * H_SZ + j;

    const float* srcI = Wih + (size_t)orig * I_SZ;
    float* dI = g_wih_p + (size_t)p * I_SZ;
    for (int k = threadIdx.x; k < I_SZ; k += blockDim.x) dI[k] = srcI[k];

    // W_hh swizzled into the scan's exact per-thread LDS.128 order:
    // CTA c owns rows [64c, 64c+64); thread tv = kq*32+rg reads rows (2rg, 2rg+1)
    // over K-range kq*64..kq*64+63; i-th float4 of the thread at float (i*256+tv)*4.
    const float* srcH = Whh + (size_t)orig * H_SZ;
    int cc = p >> 6, idx = p & 63, rg = idx >> 1, r = idx & 1;
    float* base = g_whh_sw + (size_t)cc * (64 * H_SZ);
    for (int k = threadIdx.x; k < H_SZ; k += blockDim.x) {
        int kq = k >> 6, rem = k & 63, kb = rem >> 2, ko = k & 3;
        int i  = kb * 2 + r, tv = kq * 32 + rg;
        base[(size_t)(i * 256 + tv) * 4 + ko] = srcH[k];
    }
    if (threadIdx.x == 0) g_bias_p[p] = bih[orig] + bhh[orig];

    if (p < H_SZ) {                          // transpose h0 -> [grp][0][j=p][b8]
        for (int b = threadIdx.x; b < B_SZ; b += blockDim.x)
            g_hbufT[(size_t)(b >> 3) * 2 * 8 * H_SZ + p * 8 + (b & 7)] = h0[(size_t)b * H_SZ + p];
    }
    if (p < NG && threadIdx.x == 0) g_cnt[p * 32] = 0;
    if (p < NG * NC && threadIdx.x == 0) g_genv[p * 32] = 0;
}

// ---------------- phase 1: gates_x GEMM  C[m][p] = A[m][:] . Wp[p][:] + bias[p] ----------------
#define BM 128
#define BN 64
#define BK 16
#define LDA (BM + 4)
#define LDB (BN + 4)

__global__ __launch_bounds__(256) void gemm_x_kernel(const float* __restrict__ A) {
    __shared__ float sA[BK][LDA];
    __shared__ float sB[BK][LDB];
    int tid   = threadIdx.x;
    int mBase = blockIdx.y * BM;
    int nBase = blockIdx.x * BN;
    int tm = tid & 15, tn = tid >> 4;

    int aM0 = tid >> 2;
    int aK0 = (tid & 3) * 4;
    int bN  = tid >> 2;
    int bK  = (tid & 3) * 4;

    const float* Ag = A + (size_t)mBase * I_SZ;
    const float* Bg = g_wih_p + (size_t)nBase * I_SZ;

    float4 ra0 = *(const float4*)(Ag + (size_t)aM0 * I_SZ + aK0);
    float4 ra1 = *(const float4*)(Ag + (size_t)(aM0 + 64) * I_SZ + aK0);
    float4 rb  = *(const float4*)(Bg + (size_t)bN * I_SZ + bK);

    ull acc[4][4];
#pragma unroll
    for (int u = 0; u < 4; u++)
#pragma unroll
        for (int j = 0; j < 4; j++) acc[u][j] = 0ull;

    const int KT = I_SZ / BK;
    for (int kt = 0; kt < KT; kt++) {
        sA[aK0 + 0][aM0] = ra0.x; sA[aK0 + 1][aM0] = ra0.y;
        sA[aK0 + 2][aM0] = ra0.z; sA[aK0 + 3][aM0] = ra0.w;
        sA[aK0 + 0][aM0 + 64] = ra1.x; sA[aK0 + 1][aM0 + 64] = ra1.y;
        sA[aK0 + 2][aM0 + 64] = ra1.z; sA[aK0 + 3][aM0 + 64] = ra1.w;
        sB[bK + 0][bN] = rb.x; sB[bK + 1][bN] = rb.y;
        sB[bK + 2][bN] = rb.z; sB[bK + 3][bN] = rb.w;
        __syncthreads();

        if (kt + 1 < KT) {
            int k0 = (kt + 1) * BK;
            ra0 = *(const float4*)(Ag + (size_t)aM0 * I_SZ + k0 + aK0);
            ra1 = *(const float4*)(Ag + (size_t)(aM0 + 64) * I_SZ + k0 + aK0);
            rb  = *(const float4*)(Bg + (size_t)bN * I_SZ + k0 + bK);
        }

#pragma unroll
        for (int kk = 0; kk < BK; kk++) {
            ulonglong2 a01 = *(const ulonglong2*)&sA[kk][tm * 8];
            ulonglong2 a23 = *(const ulonglong2*)&sA[kk][tm * 8 + 4];
            float4 b4 = *(const float4*)&sB[kk][tn * 4];
            ull b0 = pack2(b4.x), b1 = pack2(b4.y), b2 = pack2(b4.z), b3 = pack2(b4.w);
            ffma2(acc[0][0], a01.x, b0); ffma2(acc[0][1], a01.x, b1);
            ffma2(acc[0][2], a01.x, b2); ffma2(acc[0][3], a01.x, b3);
            ffma2(acc[1][0], a01.y, b0); ffma2(acc[1][1], a01.y, b1);
            ffma2(acc[1][2], a01.y, b2); ffma2(acc[1][3], a01.y, b3);
            ffma2(acc[2][0], a23.x, b0); ffma2(acc[2][1], a23.x, b1);
            ffma2(acc[2][2], a23.x, b2); ffma2(acc[2][3], a23.x, b3);
            ffma2(acc[3][0], a23.y, b0); ffma2(acc[3][1], a23.y, b1);
            ffma2(acc[3][2], a23.y, b2); ffma2(acc[3][3], a23.y, b3);
        }
        __syncthreads();
    }

    float4 bias = *(const float4*)&g_bias_p[nBase + tn * 4];
    float* C = g_gates + (size_t)(mBase + tm * 8) * G4 + nBase + tn * 4;
#pragma unroll
    for (int u = 0; u < 4; u++) {
        float2 c0 = unpack2(acc[u][0]);
        float2 c1 = unpack2(acc[u][1]);
        float2 c2 = unpack2(acc[u][2]);
        float2 c3 = unpack2(acc[u][3]);
        float4 lo = {c0.x + bias.x, c1.x + bias.y, c2.x + bias.z, c3.x + bias.w};
        float4 hi = {c0.y + bias.x, c1.y + bias.y, c2.y + bias.z, c3.y + bias.w};
        *(float4*)(C + (size_t)(2 * u) * G4)     = lo;
        *(float4*)(C + (size_t)(2 * u + 1) * G4) = hi;
    }
}

// ---------------- phase 2: persistent recurrent scan (R2-exact + 2 fixes) ----------------
// 4 groups x 32 CTAs. Group grp owns batches [8g, 8g+8). CTA c owns packed rows
// [64c, 64c+64) (j in [16c, 16c+16)). Thread tv = kq*32+rg: rows (2rg, 2rg+1) over
// K-eighth kq; accumulates 8 batches as packed f32x2. h transposed [j][b8].
// Barrier: atomic count; last arriver release-stores t+1 into 32 PER-CTA gen lines;
// each CTA's tid0 polls only its OWN line (no reader contention). out[] stores are
// issued AFTER the arrival atomic, so the publish fence covers only the h store.
__global__ __launch_bounds__(256) void scan_kernel(const float* __restrict__ c0,
                                                   float* __restrict__ out, int out_size) {
    extern __shared__ float smem[];
    float* sh_w    = smem;                             // 32768 floats (128 KB)
    float* sh_h    = smem + 32768;                     // 4096 floats  (16 KB) [k][b8]
    ull*   sh_part = (ull*)(smem + 32768 + 4096);      // 256*9 ull (18 KB)
    float* sh_gate = smem + 32768 + 4096 + 4608;       // 64 rows * 10 floats (2.5 KB)

    int tid = threadIdx.x;
    int grp = blockIdx.x >> 5;
    int c   = blockIdx.x & 31;
    int rg = tid & 31, kq = tid >> 5;

    // W_hh slice (pre-swizzled, conflict-free) -> SMEM once
    {
        const float4* wsrc = (const float4*)(g_whh_sw + (size_t)c * (64 * H_SZ));
        float4* wdst = (float4*)sh_w;
#pragma unroll
        for (int i = 0; i < 32; i++) wdst[tid + i * 256] = __ldg(wsrc + tid + i * 256);
    }

    int b8 = tid >> 4, jl = tid & 15;            // epilogue mapping (tid < 128)
    float c_val = 0.f;
    const float* gxp = g_gates;
    if (tid < 128) {
        c_val = c0[(size_t)(grp * 8 + b8) * H_SZ + c * 16 + jl];
        gxp   = g_gates + (size_t)(grp * 8 + b8) * G4 + c * 64 + jl * 4;
    }
    unsigned* cnt   = &g_cnt[grp * 32];
    unsigned* genv  = &g_genv[(grp * NC) * 32];        // group's 32 gen lines
    unsigned* mygen = &g_genv[(grp * NC + c) * 32];    // this CTA's line
    float* hT0 = g_hbufT + (size_t)grp * 2 * 8 * H_SZ;
    __syncthreads();

    for (int t = 0; t < T_STEPS; t++) {
        // broadcast h (L1 may be stale within launch -> .cg)
        {
            const float4* hsrc = (const float4*)(hT0 + (t & 1) * (8 * H_SZ));
            float4* hdst = (float4*)sh_h;
#pragma unroll
            for (int i = 0; i < 4; i++) hdst[tid + i * 256] = __ldcg(hsrc + tid + i * 256);
        }
        __syncthreads();

        float4 gxv = make_float4(0.f, 0.f, 0.f, 0.f);
        if (tid < 128) gxv = __ldg((const float4*)(gxp + (size_t)t * B_SZ * G4));

        ull acc[8];
#pragma unroll
        for (int i = 0; i < 8; i++) acc[i] = 0ull;

        const float4* wv = ((const float4*)sh_w) + tid;
        const ulonglong2* hv = ((const ulonglong2*)sh_h) + (kq << 7);
#pragma unroll 4
        for (int kb = 0; kb < 16; kb++) {
            float4 w0 = wv[(kb * 2 + 0) * 256];
            float4 w1 = wv[(kb * 2 + 1) * 256];
            float w0a[4] = {w0.x, w0.y, w0.z, w0.w};
            float w1a[4] = {w1.x, w1.y, w1.z, w1.w};
#pragma unroll
            for (int i = 0; i < 4; i++) {
                ulonglong2 ha = hv[(kb * 4 + i) * 2 + 0];
                ulonglong2 hb = hv[(kb * 4 + i) * 2 + 1];
                ull p0 = pack2(w0a[i]), p1 = pack2(w1a[i]);
                ffma2(acc[0], ha.x, p0); ffma2(acc[1], ha.y, p0);
                ffma2(acc[2], hb.x, p0); ffma2(acc[3], hb.y, p0);
                ffma2(acc[4], ha.x, p1); ffma2(acc[5], ha.y, p1);
                ffma2(acc[6], hb.x, p1); ffma2(acc[7], hb.y, p1);
            }
        }

        if (kq != 0) {
            ull* pp = sh_part + tid * 9;
#pragma unroll
            for (int i = 0; i < 8; i++) pp[i] = acc[i];
        }
        __syncthreads();

        if (tid < 32) {                               // kq==0 reduces 7 partials
#pragma unroll
            for (int k2 = 1; k2 < 8; k2++) {
                const ull* pp = sh_part + (k2 * 32 + tid) * 9;
#pragma unroll
                for (int i = 0; i < 8; i++) fadd2(acc[i], pp[i]);
            }
            ull* g0 = (ull*)(sh_gate + (2 * tid) * 10);
            ull* g1 = (ull*)(sh_gate + (2 * tid + 1) * 10);
#pragma unroll
            for (int j = 0; j < 4; j++) { g0[j] = acc[j]; g1[j] = acc[4 + j]; }
        }
        __syncthreads();

        float h_new = 0.f;
        if (tid < 128) {                              // epilogue: one (b, j) per thread
            const float* gr = sh_gate + (4 * jl) * 10 + b8;
            float pi = gr[0]  + gxv.x;
            float pf = gr[10] + gxv.y;
            float pg = gr[20] + gxv.z;
            float po = gr[30] + gxv.w;
            float ig = sigf(pi), fg = sigf(pf), og = sigf(po);
            float gg = tanh_fast(pg);
            c_val = fg * c_val + ig * gg;
            h_new = og * tanh_fast(c_val);
            hT0[((t + 1) & 1) * (8 * H_SZ) + (c * 16 + jl) * 8 + b8] = h_new;  // publish h
        }

        // ---- group barrier: count + per-CTA replicated gen lines ----
        __syncthreads();                              // h publish done CTA-wide
        if (tid == 0) {
            __threadfence();                          // drains only the 512B h publish
            unsigned arrived = atomicAdd(cnt, 1u) + 1u;
            if (arrived == (unsigned)(t + 1) * (unsigned)NC) {
#pragma unroll
                for (int i = 0; i < NC; i++)          // broadcast to 32 exclusive lines
                    st_rel(&genv[i * 32], (unsigned)(t + 1));
            }
        }
        // out stores drain while tid0 polls (not covered by any fence)
        if (tid < 128) {
            out[(size_t)t * BH + (size_t)(grp * 8 + b8) * H_SZ + c * 16 + jl] = h_new;
            if (t == T_STEPS - 1 && out_size >= TBH + 2 * BH) {
                out[TBH + (grp * 8 + b8) * H_SZ + c * 16 + jl]      = h_new;   // h_f
                out[TBH + BH + (grp * 8 + b8) * H_SZ + c * 16 + jl] = c_val;   // c_f
            }
        }
        if (tid == 0) {
            while (ld_acq(mygen) < (unsigned)(t + 1)) {}   // exclusive line, no contention
        }
        __syncthreads();
    }
}

// ---------------- launch ----------------
extern "C" void kernel_launch(void* const* d_in, const int* in_sizes, int n_in,
                              void* d_out, int out_size) {
    const float* input = (const float*)d_in[0];
    const float* h0    = (const float*)d_in[1];
    const float* c0    = (const float*)d_in[2];
    const float* Wih   = (const float*)d_in[3];
    const float* Whh   = (const float*)d_in[4];
    const float* bih   = (const float*)d_in[5];
    const float* bhh   = (const float*)d_in[6];
    float* out = (float*)d_out;

    prep_kernel<<<G4, 128>>>(Wih, Whh, bih, bhh, h0);

    dim3 grid(G4 / BN, (T_STEPS * B_SZ) / BM);
    gemm_x_kernel<<<grid, 256>>>(input);

    const int scan_smem = (32768 + 4096 + 4608 + 640) * (int)sizeof(float);  // 168448 B
    cudaFuncSetAttribute(scan_kernel, cudaFuncAttributeMaxDynamicSharedMemorySize, scan_smem);
    scan_kernel<<<NG * NC, 256, scan_smem>>>(c0, out, out_size);
}

// round 10
// speedup vs baseline: 3.2820x; 3.2820x over previous
#include <cuda_runtime.h>
#include <cuda_bf16.h>
#include <cstdint>

#define T_STEPS 1024
#define B_SZ    32
#define I_SZ    512
#define H_SZ    512
#define G4      2048                 // 4*H
#define TBH     (T_STEPS * B_SZ * H_SZ)
#define BH      (B_SZ * H_SZ)
#define NG      4                    // independent batch groups (8 batches each)
#define NC      32                   // CTAs per group
#define MROWS   (T_STEPS * B_SZ)     // 32768

typedef unsigned long long ull;

// ---------------- device scratch (no allocation allowed) ----------------
__device__ float g_gates[(size_t)T_STEPS * B_SZ * G4];   // [t][b][p], p = 4j+g
__device__ float g_wih_p[G4 * I_SZ];                     // packed W_ih (p = 4j+g)
__device__ float g_whh_sw[NC * 64 * H_SZ];               // per-CTA swizzled W_hh (LDS-order)
__device__ float g_bias_p[G4];                           // b_ih + b_hh, packed
__device__ float g_hbufT[NG * 2 * 8 * H_SZ];             // [grp][phase][j][b8] transposed h
__device__ unsigned g_cnt[NG * 32];                      // per-group arrival counters (padded)
__device__ unsigned g_gen2[NG * 32];                     // per-group generation (padded)
// bf16x3 GEMM operands
__device__ __nv_bfloat16 g_Ahi[(size_t)MROWS * I_SZ];
__device__ __nv_bfloat16 g_Alo[(size_t)MROWS * I_SZ];
__device__ __nv_bfloat16 g_Whi[G4 * I_SZ];
__device__ __nv_bfloat16 g_Wlo[G4 * I_SZ];

// ---------------- packed f32x2 helpers ----------------
__device__ __forceinline__ void ffma2(ull &d, ull a, ull b) {
    asm("fma.rn.f32x2 %0, %1, %2, %3;" : "=l"(d) : "l"(a), "l"(b), "l"(d));
}
__device__ __forceinline__ void fadd2(ull &d, ull a) {
    asm("add.rn.f32x2 %0, %1, %2;" : "=l"(d) : "l"(d), "l"(a));
}
__device__ __forceinline__ ull pack2(float x) {
    ull r; asm("mov.b64 %0, {%1, %1};" : "=l"(r) : "f"(x)); return r;
}
__device__ __forceinline__ float2 unpack2(ull v) {
    float2 r; asm("mov.b64 {%0, %1}, %2;" : "=f"(r.x), "=f"(r.y) : "l"(v)); return r;
}
__device__ __forceinline__ unsigned ld_acq(const unsigned* p) {
    unsigned v; asm volatile("ld.acquire.gpu.global.u32 %0, [%1];" : "=r"(v) : "l"(p) : "memory");
    return v;
}
__device__ __forceinline__ void st_rel(unsigned* p, unsigned v) {
    asm volatile("st.release.gpu.global.u32 [%0], %1;" :: "l"(p), "r"(v) : "memory");
}
__device__ __forceinline__ float sigf(float x) {
    return __fdividef(1.f, 1.f + __expf(-x));
}
__device__ __forceinline__ float tanh_fast(float x) {
    float ax = fabsf(x);
    float e  = __expf(-2.f * ax);
    float r  = __fdividef(1.f - e, 1.f + e);
    return copysignf(r, x);
}

// ---------------- prep (R2-exact): pack/swizzle weights, transpose h0, reset sync ----------
__global__ void prep_kernel(const float* __restrict__ Wih, const float* __restrict__ Whh,
                            const float* __restrict__ bih, const float* __restrict__ bhh,
                            const float* __restrict__ h0) {
    int p = blockIdx.x;                     // packed row p = 4j + g
    int g = p & 3, j = p >> 2;
    int orig = g * H_SZ + j;

    const float* srcI = Wih + (size_t)orig * I_SZ;
    float* dI = g_wih_p + (size_t)p * I_SZ;
    for (int k = threadIdx.x; k < I_SZ; k += blockDim.x) dI[k] = srcI[k];

    const float* srcH = Whh + (size_t)orig * H_SZ;
    int cc = p >> 6, idx = p & 63, rg = idx >> 1, r = idx & 1;
    float* base = g_whh_sw + (size_t)cc * (64 * H_SZ);
    for (int k = threadIdx.x; k < H_SZ; k += blockDim.x) {
        int kq = k >> 6, rem = k & 63, kb = rem >> 2, ko = k & 3;
        int i  = kb * 2 + r, tv = kq * 32 + rg;
        base[(size_t)(i * 256 + tv) * 4 + ko] = srcH[k];
    }
    if (threadIdx.x == 0) g_bias_p[p] = bih[orig] + bhh[orig];

    if (p < H_SZ) {                          // transpose h0 -> [grp][0][j=p][b8]
        for (int b = threadIdx.x; b < B_SZ; b += blockDim.x)
            g_hbufT[(size_t)(b >> 3) * 2 * 8 * H_SZ + p * 8 + (b & 7)] = h0[(size_t)b * H_SZ + p];
    }
    if (p < NG && threadIdx.x == 0) { g_cnt[p * 32] = 0; g_gen2[p * 32] = 0; }
}

// ---------------- convert: fp32 -> bf16 hi/lo for A (input) and packed W_ih ------------
__global__ __launch_bounds__(256) void convert_kernel(const float* __restrict__ input) {
    int bid = blockIdx.x;
    const float* src;
    __nv_bfloat16 *dhi, *dlo;
    size_t i;
    if (bid < 8192) {                        // A: 32768x512 fp32
        i = ((size_t)bid * 256 + threadIdx.x) * 8;
        src = input; dhi = g_Ahi; dlo = g_Alo;
    } else {                                 // W: 2048x512 (packed)
        i = ((size_t)(bid - 8192) * 256 + threadIdx.x) * 8;
        src = g_wih_p; dhi = g_Whi; dlo = g_Wlo;
    }
    float4 x0 = *(const float4*)(src + i);
    float4 x1 = *(const float4*)(src + i + 4);
    float v[8] = {x0.x, x0.y, x0.z, x0.w, x1.x, x1.y, x1.z, x1.w};
    unsigned hs[4], ls[4];
#pragma unroll
    for (int k = 0; k < 4; k++) {
        __nv_bfloat16 h0 = __float2bfloat16(v[2 * k]);
        __nv_bfloat16 h1 = __float2bfloat16(v[2 * k + 1]);
        __nv_bfloat16 l0 = __float2bfloat16(v[2 * k]     - __bfloat162float(h0));
        __nv_bfloat16 l1 = __float2bfloat16(v[2 * k + 1] - __bfloat162float(h1));
        hs[k] = (unsigned)__bfloat16_as_ushort(h0) | ((unsigned)__bfloat16_as_ushort(h1) << 16);
        ls[k] = (unsigned)__bfloat16_as_ushort(l0) | ((unsigned)__bfloat16_as_ushort(l1) << 16);
    }
    *(uint4*)(dhi + i) = make_uint4(hs[0], hs[1], hs[2], hs[3]);
    *(uint4*)(dlo + i) = make_uint4(ls[0], ls[1], ls[2], ls[3]);
}

// ---------------- phase 1: bf16x3 HMMA GEMM -> g_gates[m][p] + bias ----------------
// mma.sync.m16n8k16 (plain sm_80+ PTX; no 'a'-target features).
// Block tile 128m x 128n, 8 warps (4m x 2n), warp tile 32m x 64n, K chunk 32.
// D = Ahi*Bhi + Ahi*Blo + Alo*Bhi, fp32 accum.
#define GPITCH 40   // smem row pitch in bf16 (80B): fragment loads provably conflict-free

__device__ __forceinline__ void mma16816(float* c, const unsigned* a, const unsigned* b) {
    asm volatile(
        "mma.sync.aligned.m16n8k16.row.col.f32.bf16.bf16.f32 "
        "{%0,%1,%2,%3}, {%4,%5,%6,%7}, {%8,%9}, {%0,%1,%2,%3};"
        : "+f"(c[0]), "+f"(c[1]), "+f"(c[2]), "+f"(c[3])
        : "r"(a[0]), "r"(a[1]), "r"(a[2]), "r"(a[3]), "r"(b[0]), "r"(b[1]));
}

__global__ __launch_bounds__(256) void gemm_tc_kernel() {
    __shared__ __nv_bfloat16 sAh[128][GPITCH];
    __shared__ __nv_bfloat16 sAl[128][GPITCH];
    __shared__ __nv_bfloat16 sBh[128][GPITCH];
    __shared__ __nv_bfloat16 sBl[128][GPITCH];

    int tid  = threadIdx.x;
    int lane = tid & 31, wid = tid >> 5;
    int wm = wid & 3, wn = wid >> 2;            // warp tile: (wm*32, wn*64)
    int mBase = blockIdx.y * 128;
    int nBase = blockIdx.x * 128;

    int lrow = tid >> 1, lhalf = tid & 1;       // loader mapping: 128 rows x 2 halves

    float acc[2][8][4];
#pragma unroll
    for (int ma = 0; ma < 2; ma++)
#pragma unroll
        for (int na = 0; na < 8; na++)
#pragma unroll
            for (int q = 0; q < 4; q++) acc[ma][na][q] = 0.f;

    int fr = lane >> 2;                         // fragment row/col components
    int fc = (lane & 3) * 2;

    for (int ks = 0; ks < I_SZ / 32; ks++) {
        // ---- stage chunk ks (A: 128x32 hi/lo, B: 128x32 hi/lo) ----
        {
            size_t ga = (size_t)(mBase + lrow) * I_SZ + ks * 32 + lhalf * 16;
            const uint4* pa = (const uint4*)(g_Ahi + ga);
            uint4 a0 = __ldg(pa), a1 = __ldg(pa + 1);
            *(uint4*)&sAh[lrow][lhalf * 16]     = a0;
            *(uint4*)&sAh[lrow][lhalf * 16 + 8] = a1;
            const uint4* pl = (const uint4*)(g_Alo + ga);
            uint4 l0 = __ldg(pl), l1 = __ldg(pl + 1);
            *(uint4*)&sAl[lrow][lhalf * 16]     = l0;
            *(uint4*)&sAl[lrow][lhalf * 16 + 8] = l1;
            size_t gb = (size_t)(nBase + lrow) * I_SZ + ks * 32 + lhalf * 16;
            const uint4* pb = (const uint4*)(g_Whi + gb);
            uint4 b0 = __ldg(pb), b1 = __ldg(pb + 1);
            *(uint4*)&sBh[lrow][lhalf * 16]     = b0;
            *(uint4*)&sBh[lrow][lhalf * 16 + 8] = b1;
            const uint4* pq = (const uint4*)(g_Wlo + gb);
            uint4 q0 = __ldg(pq), q1 = __ldg(pq + 1);
            *(uint4*)&sBl[lrow][lhalf * 16]     = q0;
            *(uint4*)&sBl[lrow][lhalf * 16 + 8] = q1;
        }
        __syncthreads();

#pragma unroll
        for (int ka = 0; ka < 2; ka++) {        // two k16 atoms per chunk
            int kc = ka * 16 + fc;
            // A fragments (hi & lo) for both m atoms
            unsigned aH[2][4], aL[2][4];
#pragma unroll
            for (int ma = 0; ma < 2; ma++) {
                int r0 = wm * 32 + ma * 16 + fr;
                aH[ma][0] = *(const unsigned*)&sAh[r0][kc];
                aH[ma][1] = *(const unsigned*)&sAh[r0 + 8][kc];
                aH[ma][2] = *(const unsigned*)&sAh[r0][kc + 8];
                aH[ma][3] = *(const unsigned*)&sAh[r0 + 8][kc + 8];
                aL[ma][0] = *(const unsigned*)&sAl[r0][kc];
                aL[ma][1] = *(const unsigned*)&sAl[r0 + 8][kc];
                aL[ma][2] = *(const unsigned*)&sAl[r0][kc + 8];
                aL[ma][3] = *(const unsigned*)&sAl[r0 + 8][kc + 8];
            }
            // B fragments (hi & lo) for 8 n atoms
            unsigned bH[8][2], bL[8][2];
#pragma unroll
            for (int na = 0; na < 8; na++) {
                int n0 = wn * 64 + na * 8 + fr;
                bH[na][0] = *(const unsigned*)&sBh[n0][kc];
                bH[na][1] = *(const unsigned*)&sBh[n0][kc + 8];
                bL[na][0] = *(const unsigned*)&sBl[n0][kc];
                bL[na][1] = *(const unsigned*)&sBl[n0][kc + 8];
            }
#pragma unroll
            for (int ma = 0; ma < 2; ma++)
#pragma unroll
                for (int na = 0; na < 8; na++) {
                    mma16816(acc[ma][na], aH[ma], bH[na]);
                    mma16816(acc[ma][na], aH[ma], bL[na]);
                    mma16816(acc[ma][na], aL[ma], bH[na]);
                }
        }
        __syncthreads();
    }

    // ---- epilogue: bias + store fp32 gates ----
#pragma unroll
    for (int ma = 0; ma < 2; ma++)
#pragma unroll
        for (int na = 0; na < 8; na++) {
            int row = mBase + wm * 32 + ma * 16 + fr;
            int col = nBase + wn * 64 + na * 8 + fc;
            float b0 = __ldg(&g_bias_p[col]);
            float b1 = __ldg(&g_bias_p[col + 1]);
            float* d0 = g_gates + (size_t)row * G4 + col;
            d0[0] = acc[ma][na][0] + b0;
            d0[1] = acc[ma][na][1] + b1;
            float* d1 = d0 + (size_t)8 * G4;
            d1[0] = acc[ma][na][2] + b0;
            d1[1] = acc[ma][na][3] + b1;
        }
}

// ---------------- phase 2: persistent recurrent scan (R2-EXACT, best known) ----------------
__global__ __launch_bounds__(256) void scan_kernel(const float* __restrict__ c0,
                                                   float* __restrict__ out, int out_size) {
    extern __shared__ float smem[];
    float* sh_w    = smem;                             // 32768 floats (128 KB)
    float* sh_h    = smem + 32768;                     // 4096 floats  (16 KB) [k][b8]
    ull*   sh_part = (ull*)(smem + 32768 + 4096);      // 256*9 ull (18 KB)
    float* sh_gate = smem + 32768 + 4096 + 4608;       // 64 rows * 10 floats (2.5 KB)

    int tid = threadIdx.x;
    int grp = blockIdx.x >> 5;
    int c   = blockIdx.x & 31;
    int kq = tid >> 5;

    {
        const float4* wsrc = (const float4*)(g_whh_sw + (size_t)c * (64 * H_SZ));
        float4* wdst = (float4*)sh_w;
#pragma unroll
        for (int i = 0; i < 32; i++) wdst[tid + i * 256] = __ldg(wsrc + tid + i * 256);
    }

    int b8 = tid >> 4, jl = tid & 15;            // epilogue mapping (tid < 128)
    float c_val = 0.f;
    const float* gxp = g_gates;
    if (tid < 128) {
        c_val = c0[(size_t)(grp * 8 + b8) * H_SZ + c * 16 + jl];
        gxp   = g_gates + (size_t)(grp * 8 + b8) * G4 + c * 64 + jl * 4;
    }
    unsigned* cnt = &g_cnt[grp * 32];
    unsigned* gen = &g_gen2[grp * 32];
    float* hT0 = g_hbufT + (size_t)grp * 2 * 8 * H_SZ;

    for (int t = 0; t < T_STEPS; t++) {
        {
            const float4* hsrc = (const float4*)(hT0 + (t & 1) * (8 * H_SZ));
#pragma unroll
            for (int i = 0; i < 4; i++)
                ((float4*)sh_h)[tid + i * 256] = __ldcg(hsrc + tid + i * 256);
        }
        __syncthreads();

        float4 gxv = make_float4(0.f, 0.f, 0.f, 0.f);
        if (tid < 128) gxv = __ldg((const float4*)(gxp + (size_t)t * B_SZ * G4));

        ull acc[8];
#pragma unroll
        for (int i = 0; i < 8; i++) acc[i] = 0ull;

        const float4* wv = ((const float4*)sh_w) + tid;
        const ulonglong2* hv = ((const ulonglong2*)sh_h) + (kq << 7);
#pragma unroll 4
        for (int kb = 0; kb < 16; kb++) {
            float4 w0 = wv[(kb * 2 + 0) * 256];
            float4 w1 = wv[(kb * 2 + 1) * 256];
            float w0a[4] = {w0.x, w0.y, w0.z, w0.w};
            float w1a[4] = {w1.x, w1.y, w1.z, w1.w};
#pragma unroll
            for (int i = 0; i < 4; i++) {
                ulonglong2 ha = hv[(kb * 4 + i) * 2 + 0];
                ulonglong2 hb = hv[(kb * 4 + i) * 2 + 1];
                ull p0 = pack2(w0a[i]), p1 = pack2(w1a[i]);
                ffma2(acc[0], ha.x, p0); ffma2(acc[1], ha.y, p0);
                ffma2(acc[2], hb.x, p0); ffma2(acc[3], hb.y, p0);
                ffma2(acc[4], ha.x, p1); ffma2(acc[5], ha.y, p1);
                ffma2(acc[6], hb.x, p1); ffma2(acc[7], hb.y, p1);
            }
        }

        if (kq != 0) {
            ull* pp = sh_part + tid * 9;
#pragma unroll
            for (int i = 0; i < 8; i++) pp[i] = acc[i];
        }
        __syncthreads();

        if (tid < 32) {
#pragma unroll
            for (int k2 = 1; k2 < 8; k2++) {
                const ull* pp = sh_part + (k2 * 32 + tid) * 9;
#pragma unroll
                for (int i = 0; i < 8; i++) fadd2(acc[i], pp[i]);
            }
            ull* g0 = (ull*)(sh_gate + (2 * tid) * 10);
            ull* g1 = (ull*)(sh_gate + (2 * tid + 1) * 10);
#pragma unroll
            for (int j = 0; j < 4; j++) { g0[j] = acc[j]; g1[j] = acc[4 + j]; }
        }
        __syncthreads();

        if (tid < 128) {
            const float* gr = sh_gate + (4 * jl) * 10 + b8;
            float pi = gr[0]  + gxv.x;
            float pf = gr[10] + gxv.y;
            float pg = gr[20] + gxv.z;
            float po = gr[30] + gxv.w;
            float ig = sigf(pi), fg = sigf(pf), og = sigf(po);
            float gg = tanh_fast(pg);
            c_val = fg * c_val + ig * gg;
            float h_new = og * tanh_fast(c_val);
            hT0[((t + 1) & 1) * (8 * H_SZ) + (c * 16 + jl) * 8 + b8] = h_new;
            out[(size_t)t * BH + (size_t)(grp * 8 + b8) * H_SZ + c * 16 + jl] = h_new;
            if (t == T_STEPS - 1 && out_size >= TBH + 2 * BH) {
                out[TBH + (grp * 8 + b8) * H_SZ + c * 16 + jl]      = h_new;  // h_f
                out[TBH + BH + (grp * 8 + b8) * H_SZ + c * 16 + jl] = c_val;  // c_f
            }
        }

        // ---- group barrier: monotonic count + release/acquire gen, pure spin ----
        __syncthreads();
        if (tid == 0) {
            __threadfence();
            unsigned arrived = atomicAdd(cnt, 1u) + 1u;
            if (arrived == (unsigned)(t + 1) * (unsigned)NC) {
                st_rel(gen, (unsigned)(t + 1));
            } else {
                while (ld_acq(gen) < (unsigned)(t + 1)) {}
            }
        }
        __syncthreads();
    }
}

// ---------------- launch ----------------
extern "C" void kernel_launch(void* const* d_in, const int* in_sizes, int n_in,
                              void* d_out, int out_size) {
    const float* input = (const float*)d_in[0];
    const float* h0    = (const float*)d_in[1];
    const float* c0    = (const float*)d_in[2];
    const float* Wih   = (const float*)d_in[3];
    const float* Whh   = (const float*)d_in[4];
    const float* bih   = (const float*)d_in[5];
    const float* bhh   = (const float*)d_in[6];
    float* out = (float*)d_out;

    prep_kernel<<<G4, 128>>>(Wih, Whh, bih, bhh, h0);
    convert_kernel<<<8192 + 512, 256>>>(input);

    dim3 gridG(G4 / 128, MROWS / 128);
    gemm_tc_kernel<<<gridG, 256>>>();

    const int scan_smem = (32768 + 4096 + 4608 + 640) * (int)sizeof(float);  // 168448 B
    cudaFuncSetAttribute(scan_kernel, cudaFuncAttributeMaxDynamicSharedMemorySize, scan_smem);
    scan_kernel<<<NG * NC, 256, scan_smem>>>(c0, out, out_size);
}

// round 11
// speedup vs baseline: 3.6690x; 1.1179x over previous
#include <cuda_runtime.h>
#include <cuda_bf16.h>
#include <cstdint>

#define T_STEPS 1024
#define B_SZ    32
#define I_SZ    512
#define H_SZ    512
#define G4      2048                 // 4*H
#define TBH     (T_STEPS * B_SZ * H_SZ)
#define BH      (B_SZ * H_SZ)
#define NG      4                    // independent batch groups (8 batches each)
#define NC      32                   // CTAs per group
#define MROWS   (T_STEPS * B_SZ)     // 32768

typedef unsigned long long ull;

// ---------------- device scratch (no allocation allowed) ----------------
__device__ float g_gates[(size_t)T_STEPS * B_SZ * G4];   // [t][b][p], p = 4j+g
__device__ float g_wih_p[G4 * I_SZ];                     // packed W_ih (p = 4j+g)
__device__ float g_whh_sw[NC * 64 * H_SZ];               // per-CTA swizzled W_hh (reg-load order)
__device__ float g_bias_p[G4];                           // b_ih + b_hh, packed
__device__ float g_hbufT[NG * 2 * 8 * H_SZ];             // [grp][phase][j][b8] transposed h
__device__ unsigned g_cnt[NG * 32];                      // per-group arrival counters (padded)
__device__ unsigned g_gen2[NG * 32];                     // per-group generation (padded)
// bf16x3 GEMM operands
__device__ __nv_bfloat16 g_Ahi[(size_t)MROWS * I_SZ];
__device__ __nv_bfloat16 g_Alo[(size_t)MROWS * I_SZ];
__device__ __nv_bfloat16 g_Whi[G4 * I_SZ];
__device__ __nv_bfloat16 g_Wlo[G4 * I_SZ];

// ---------------- packed f32x2 helpers ----------------
__device__ __forceinline__ void ffma2(ull &d, ull a, ull b) {
    asm("fma.rn.f32x2 %0, %1, %2, %3;" : "=l"(d) : "l"(a), "l"(b), "l"(d));
}
__device__ __forceinline__ void fadd2(ull &d, ull a) {
    asm("add.rn.f32x2 %0, %1, %2;" : "=l"(d) : "l"(d), "l"(a));
}
__device__ __forceinline__ ull pack2(float x) {
    ull r; asm("mov.b64 %0, {%1, %1};" : "=l"(r) : "f"(x)); return r;
}
__device__ __forceinline__ float2 unpack2(ull v) {
    float2 r; asm("mov.b64 {%0, %1}, %2;" : "=f"(r.x), "=f"(r.y) : "l"(v)); return r;
}
__device__ __forceinline__ unsigned ld_acq(const unsigned* p) {
    unsigned v; asm volatile("ld.acquire.gpu.global.u32 %0, [%1];" : "=r"(v) : "l"(p) : "memory");
    return v;
}
__device__ __forceinline__ void st_rel(unsigned* p, unsigned v) {
    asm volatile("st.release.gpu.global.u32 [%0], %1;" :: "l"(p), "r"(v) : "memory");
}
__device__ __forceinline__ unsigned atom_add_rel(unsigned* p, unsigned v) {
    unsigned old;
    asm volatile("atom.add.release.gpu.global.u32 %0, [%1], %2;"
                 : "=r"(old) : "l"(p), "r"(v) : "memory");
    return old;
}
__device__ __forceinline__ float sigf(float x) {
    return __fdividef(1.f, 1.f + __expf(-x));
}
__device__ __forceinline__ float tanh_fast(float x) {
    float ax = fabsf(x);
    float e  = __expf(-2.f * ax);
    float r  = __fdividef(1.f - e, 1.f + e);
    return copysignf(r, x);
}

// ---------------- prep (R2-exact): pack/swizzle weights, transpose h0, reset sync ----------
__global__ void prep_kernel(const float* __restrict__ Wih, const float* __restrict__ Whh,
                            const float* __restrict__ bih, const float* __restrict__ bhh,
                            const float* __restrict__ h0) {
    int p = blockIdx.x;                     // packed row p = 4j + g
    int g = p & 3, j = p >> 2;
    int orig = g * H_SZ + j;

    const float* srcI = Wih + (size_t)orig * I_SZ;
    float* dI = g_wih_p + (size_t)p * I_SZ;
    for (int k = threadIdx.x; k < I_SZ; k += blockDim.x) dI[k] = srcI[k];

    const float* srcH = Whh + (size_t)orig * H_SZ;
    int cc = p >> 6, idx = p & 63, rg = idx >> 1, r = idx & 1;
    float* base = g_whh_sw + (size_t)cc * (64 * H_SZ);
    for (int k = threadIdx.x; k < H_SZ; k += blockDim.x) {
        int kq = k >> 6, rem = k & 63, kb = rem >> 2, ko = k & 3;
        int i  = kb * 2 + r, tv = kq * 32 + rg;
        base[(size_t)(i * 256 + tv) * 4 + ko] = srcH[k];
    }
    if (threadIdx.x == 0) g_bias_p[p] = bih[orig] + bhh[orig];

    if (p < H_SZ) {                          // transpose h0 -> [grp][0][j=p][b8]
        for (int b = threadIdx.x; b < B_SZ; b += blockDim.x)
            g_hbufT[(size_t)(b >> 3) * 2 * 8 * H_SZ + p * 8 + (b & 7)] = h0[(size_t)b * H_SZ + p];
    }
    if (p < NG && threadIdx.x == 0) { g_cnt[p * 32] = 0; g_gen2[p * 32] = 0; }
}

// ---------------- convert: fp32 -> bf16 hi/lo for A (input) and packed W_ih ------------
__global__ __launch_bounds__(256) void convert_kernel(const float* __restrict__ input) {
    int bid = blockIdx.x;
    const float* src;
    __nv_bfloat16 *dhi, *dlo;
    size_t i;
    if (bid < 8192) {                        // A: 32768x512 fp32
        i = ((size_t)bid * 256 + threadIdx.x) * 8;
        src = input; dhi = g_Ahi; dlo = g_Alo;
    } else {                                 // W: 2048x512 (packed)
        i = ((size_t)(bid - 8192) * 256 + threadIdx.x) * 8;
        src = g_wih_p; dhi = g_Whi; dlo = g_Wlo;
    }
    float4 x0 = *(const float4*)(src + i);
    float4 x1 = *(const float4*)(src + i + 4);
    float v[8] = {x0.x, x0.y, x0.z, x0.w, x1.x, x1.y, x1.z, x1.w};
    unsigned hs[4], ls[4];
#pragma unroll
    for (int k = 0; k < 4; k++) {
        __nv_bfloat16 h0 = __float2bfloat16(v[2 * k]);
        __nv_bfloat16 h1 = __float2bfloat16(v[2 * k + 1]);
        __nv_bfloat16 l0 = __float2bfloat16(v[2 * k]     - __bfloat162float(h0));
        __nv_bfloat16 l1 = __float2bfloat16(v[2 * k + 1] - __bfloat162float(h1));
        hs[k] = (unsigned)__bfloat16_as_ushort(h0) | ((unsigned)__bfloat16_as_ushort(h1) << 16);
        ls[k] = (unsigned)__bfloat16_as_ushort(l0) | ((unsigned)__bfloat16_as_ushort(l1) << 16);
    }
    *(uint4*)(dhi + i) = make_uint4(hs[0], hs[1], hs[2], hs[3]);
    *(uint4*)(dlo + i) = make_uint4(ls[0], ls[1], ls[2], ls[3]);
}

// ---------------- phase 1: bf16x3 HMMA GEMM -> g_gates[m][p] + bias (R10-exact) --------
#define GPITCH 40   // smem row pitch in bf16 (80B): fragment loads conflict-free

__device__ __forceinline__ void mma16816(float* c, const unsigned* a, const unsigned* b) {
    asm volatile(
        "mma.sync.aligned.m16n8k16.row.col.f32.bf16.bf16.f32 "
        "{%0,%1,%2,%3}, {%4,%5,%6,%7}, {%8,%9}, {%0,%1,%2,%3};"
        : "+f"(c[0]), "+f"(c[1]), "+f"(c[2]), "+f"(c[3])
        : "r"(a[0]), "r"(a[1]), "r"(a[2]), "r"(a[3]), "r"(b[0]), "r"(b[1]));
}

__global__ __launch_bounds__(256) void gemm_tc_kernel() {
    __shared__ __nv_bfloat16 sAh[128][GPITCH];
    __shared__ __nv_bfloat16 sAl[128][GPITCH];
    __shared__ __nv_bfloat16 sBh[128][GPITCH];
    __shared__ __nv_bfloat16 sBl[128][GPITCH];

    int tid  = threadIdx.x;
    int lane = tid & 31, wid = tid >> 5;
    int wm = wid & 3, wn = wid >> 2;            // warp tile: (wm*32, wn*64)
    int mBase = blockIdx.y * 128;
    int nBase = blockIdx.x * 128;

    int lrow = tid >> 1, lhalf = tid & 1;       // loader mapping: 128 rows x 2 halves

    float acc[2][8][4];
#pragma unroll
    for (int ma = 0; ma < 2; ma++)
#pragma unroll
        for (int na = 0; na < 8; na++)
#pragma unroll
            for (int q = 0; q < 4; q++) acc[ma][na][q] = 0.f;

    int fr = lane >> 2;                         // fragment row/col components
    int fc = (lane & 3) * 2;

    for (int ks = 0; ks < I_SZ / 32; ks++) {
        {
            size_t ga = (size_t)(mBase + lrow) * I_SZ + ks * 32 + lhalf * 16;
            const uint4* pa = (const uint4*)(g_Ahi + ga);
            uint4 a0 = __ldg(pa), a1 = __ldg(pa + 1);
            *(uint4*)&sAh[lrow][lhalf * 16]     = a0;
            *(uint4*)&sAh[lrow][lhalf * 16 + 8] = a1;
            const uint4* pl = (const uint4*)(g_Alo + ga);
            uint4 l0 = __ldg(pl), l1 = __ldg(pl + 1);
            *(uint4*)&sAl[lrow][lhalf * 16]     = l0;
            *(uint4*)&sAl[lrow][lhalf * 16 + 8] = l1;
            size_t gb = (size_t)(nBase + lrow) * I_SZ + ks * 32 + lhalf * 16;
            const uint4* pb = (const uint4*)(g_Whi + gb);
            uint4 b0 = __ldg(pb), b1 = __ldg(pb + 1);
            *(uint4*)&sBh[lrow][lhalf * 16]     = b0;
            *(uint4*)&sBh[lrow][lhalf * 16 + 8] = b1;
            const uint4* pq = (const uint4*)(g_Wlo + gb);
            uint4 q0 = __ldg(pq), q1 = __ldg(pq + 1);
            *(uint4*)&sBl[lrow][lhalf * 16]     = q0;
            *(uint4*)&sBl[lrow][lhalf * 16 + 8] = q1;
        }
        __syncthreads();

#pragma unroll
        for (int ka = 0; ka < 2; ka++) {        // two k16 atoms per chunk
            int kc = ka * 16 + fc;
            unsigned aH[2][4], aL[2][4];
#pragma unroll
            for (int ma = 0; ma < 2; ma++) {
                int r0 = wm * 32 + ma * 16 + fr;
                aH[ma][0] = *(const unsigned*)&sAh[r0][kc];
                aH[ma][1] = *(const unsigned*)&sAh[r0 + 8][kc];
                aH[ma][2] = *(const unsigned*)&sAh[r0][kc + 8];
                aH[ma][3] = *(const unsigned*)&sAh[r0 + 8][kc + 8];
                aL[ma][0] = *(const unsigned*)&sAl[r0][kc];
                aL[ma][1] = *(const unsigned*)&sAl[r0 + 8][kc];
                aL[ma][2] = *(const unsigned*)&sAl[r0][kc + 8];
                aL[ma][3] = *(const unsigned*)&sAl[r0 + 8][kc + 8];
            }
            unsigned bH[8][2], bL[8][2];
#pragma unroll
            for (int na = 0; na < 8; na++) {
                int n0 = wn * 64 + na * 8 + fr;
                bH[na][0] = *(const unsigned*)&sBh[n0][kc];
                bH[na][1] = *(const unsigned*)&sBh[n0][kc + 8];
                bL[na][0] = *(const unsigned*)&sBl[n0][kc];
                bL[na][1] = *(const unsigned*)&sBl[n0][kc + 8];
            }
#pragma unroll
            for (int ma = 0; ma < 2; ma++)
#pragma unroll
                for (int na = 0; na < 8; na++) {
                    mma16816(acc[ma][na], aH[ma], bH[na]);
                    mma16816(acc[ma][na], aH[ma], bL[na]);
                    mma16816(acc[ma][na], aL[ma], bH[na]);
                }
        }
        __syncthreads();
    }

#pragma unroll
    for (int ma = 0; ma < 2; ma++)
#pragma unroll
        for (int na = 0; na < 8; na++) {
            int row = mBase + wm * 32 + ma * 16 + fr;
            int col = nBase + wn * 64 + na * 8 + fc;
            float b0 = __ldg(&g_bias_p[col]);
            float b1 = __ldg(&g_bias_p[col + 1]);
            float* d0 = g_gates + (size_t)row * G4 + col;
            d0[0] = acc[ma][na][0] + b0;
            d0[1] = acc[ma][na][1] + b1;
            float* d1 = d0 + (size_t)8 * G4;
            d1[0] = acc[ma][na][2] + b0;
            d1[1] = acc[ma][na][3] + b1;
        }
}

// ---------------- phase 2: persistent recurrent scan (R2 structure, W in REGISTERS) ----
// Identical thread mapping, arithmetic order, and sync to the 6804us R2 scan, except:
//  (a) each thread's 128 constant W values live in 32 float4 REGISTERS (loaded once),
//      eliminating 32 LDS.128/thread/step of crossbar traffic;
//  (b) fence+atomicAdd fused into one atom.add.release.gpu.
__global__ __launch_bounds__(256) void scan_kernel(const float* __restrict__ c0,
                                                   float* __restrict__ out, int out_size) {
    extern __shared__ float smem[];
    float* sh_h    = smem;                          // 4096 floats (16 KB) [k][b8]
    ull*   sh_part = (ull*)(smem + 4096);           // 256*9 ull (18 KB)
    float* sh_gate = smem + 4096 + 4608;            // 64 rows * 10 floats (2.5 KB)

    int tid = threadIdx.x;
    int grp = blockIdx.x >> 5;
    int c   = blockIdx.x & 31;
    int kq  = tid >> 5;

    // W_hh slice -> REGISTERS (constant for all 1024 steps; same values/order as R2)
    float4 w4[32];
    {
        const float4* wsrc = (const float4*)(g_whh_sw + (size_t)c * (64 * H_SZ));
#pragma unroll
        for (int i = 0; i < 32; i++) w4[i] = __ldg(wsrc + tid + i * 256);
    }

    int b8 = tid >> 4, jl = tid & 15;            // epilogue mapping (tid < 128)
    float c_val = 0.f;
    const float* gxp = g_gates;
    if (tid < 128) {
        c_val = c0[(size_t)(grp * 8 + b8) * H_SZ + c * 16 + jl];
        gxp   = g_gates + (size_t)(grp * 8 + b8) * G4 + c * 64 + jl * 4;
    }
    unsigned* cnt = &g_cnt[grp * 32];
    unsigned* gen = &g_gen2[grp * 32];
    float* hT0 = g_hbufT + (size_t)grp * 2 * 8 * H_SZ;

    for (int t = 0; t < T_STEPS; t++) {
        {
            const float4* hsrc = (const float4*)(hT0 + (t & 1) * (8 * H_SZ));
#pragma unroll
            for (int i = 0; i < 4; i++)
                ((float4*)sh_h)[tid + i * 256] = __ldcg(hsrc + tid + i * 256);
        }
        __syncthreads();

        float4 gxv = make_float4(0.f, 0.f, 0.f, 0.f);
        if (tid < 128) gxv = __ldg((const float4*)(gxp + (size_t)t * B_SZ * G4));

        ull acc[8];
#pragma unroll
        for (int i = 0; i < 8; i++) acc[i] = 0ull;

        const ulonglong2* hv = ((const ulonglong2*)sh_h) + (kq << 7);
#pragma unroll
        for (int kb = 0; kb < 16; kb++) {
            float4 w0 = w4[kb * 2 + 0];
            float4 w1 = w4[kb * 2 + 1];
            float w0a[4] = {w0.x, w0.y, w0.z, w0.w};
            float w1a[4] = {w1.x, w1.y, w1.z, w1.w};
#pragma unroll
            for (int i = 0; i < 4; i++) {
                ulonglong2 ha = hv[(kb * 4 + i) * 2 + 0];
                ulonglong2 hb = hv[(kb * 4 + i) * 2 + 1];
                ull p0 = pack2(w0a[i]), p1 = pack2(w1a[i]);
                ffma2(acc[0], ha.x, p0); ffma2(acc[1], ha.y, p0);
                ffma2(acc[2], hb.x, p0); ffma2(acc[3], hb.y, p0);
                ffma2(acc[4], ha.x, p1); ffma2(acc[5], ha.y, p1);
                ffma2(acc[6], hb.x, p1); ffma2(acc[7], hb.y, p1);
            }
        }

        if (kq != 0) {
            ull* pp = sh_part + tid * 9;
#pragma unroll
            for (int i = 0; i < 8; i++) pp[i] = acc[i];
        }
        __syncthreads();

        if (tid < 32) {
#pragma unroll
            for (int k2 = 1; k2 < 8; k2++) {
                const ull* pp = sh_part + (k2 * 32 + tid) * 9;
#pragma unroll
                for (int i = 0; i < 8; i++) fadd2(acc[i], pp[i]);
            }
            ull* g0 = (ull*)(sh_gate + (2 * tid) * 10);
            ull* g1 = (ull*)(sh_gate + (2 * tid + 1) * 10);
#pragma unroll
            for (int j = 0; j < 4; j++) { g0[j] = acc[j]; g1[j] = acc[4 + j]; }
        }
        __syncthreads();

        if (tid < 128) {
            const float* gr = sh_gate + (4 * jl) * 10 + b8;
            float pi = gr[0]  + gxv.x;
            float pf = gr[10] + gxv.y;
            float pg = gr[20] + gxv.z;
            float po = gr[30] + gxv.w;
            float ig = sigf(pi), fg = sigf(pf), og = sigf(po);
            float gg = tanh_fast(pg);
            c_val = fg * c_val + ig * gg;
            float h_new = og * tanh_fast(c_val);
            hT0[((t + 1) & 1) * (8 * H_SZ) + (c * 16 + jl) * 8 + b8] = h_new;
            out[(size_t)t * BH + (size_t)(grp * 8 + b8) * H_SZ + c * 16 + jl] = h_new;
            if (t == T_STEPS - 1 && out_size >= TBH + 2 * BH) {
                out[TBH + (grp * 8 + b8) * H_SZ + c * 16 + jl]      = h_new;  // h_f
                out[TBH + BH + (grp * 8 + b8) * H_SZ + c * 16 + jl] = c_val;  // c_f
            }
        }

        // ---- group barrier: release-atomic count + gen word, pure spin ----
        __syncthreads();
        if (tid == 0) {
            unsigned arrived = atom_add_rel(cnt, 1u) + 1u;
            if (arrived == (unsigned)(t + 1) * (unsigned)NC) {
                st_rel(gen, (unsigned)(t + 1));
            } else {
                while (ld_acq(gen) < (unsigned)(t + 1)) {}
            }
        }
        __syncthreads();
    }
}

// ---------------- launch ----------------
extern "C" void kernel_launch(void* const* d_in, const int* in_sizes, int n_in,
                              void* d_out, int out_size) {
    const float* input = (const float*)d_in[0];
    const float* h0    = (const float*)d_in[1];
    const float* c0    = (const float*)d_in[2];
    const float* Wih   = (const float*)d_in[3];
    const float* Whh   = (const float*)d_in[4];
    const float* bih   = (const float*)d_in[5];
    const float* bhh   = (const float*)d_in[6];
    float* out = (float*)d_out;

    prep_kernel<<<G4, 128>>>(Wih, Whh, bih, bhh, h0);
    convert_kernel<<<8192 + 512, 256>>>(input);

    dim3 gridG(G4 / 128, MROWS / 128);
    gemm_tc_kernel<<<gridG, 256>>>();

    const int scan_smem = (4096 + 4608 + 640) * (int)sizeof(float);  // 37376 B
    cudaFuncSetAttribute(scan_kernel, cudaFuncAttributeMaxDynamicSharedMemorySize, scan_smem);
    scan_kernel<<<NG * NC, 256, scan_smem>>>(c0, out, out_size);
}

// round 12
// speedup vs baseline: 3.7153x; 1.0126x over previous
#include <cuda_runtime.h>
#include <cuda_bf16.h>
#include <cstdint>

#define T_STEPS 1024
#define B_SZ    32
#define I_SZ    512
#define H_SZ    512
#define G4      2048                 // 4*H
#define TBH     (T_STEPS * B_SZ * H_SZ)
#define BH      (B_SZ * H_SZ)
#define NG      4                    // independent batch groups (8 batches each)
#define NC      32                   // CTAs per group
#define NCH     16                   // CTAs per half-barrier
#define MROWS   (T_STEPS * B_SZ)     // 32768

typedef unsigned long long ull;

// ---------------- device scratch (no allocation allowed) ----------------
__device__ float g_gates[(size_t)T_STEPS * B_SZ * G4];   // [t][b][p], p = 4j+g
__device__ float g_wih_p[G4 * I_SZ];                     // packed W_ih (p = 4j+g)
__device__ float g_whh_sw[NC * 64 * H_SZ];               // per-CTA swizzled W_hh (reg-load order)
__device__ float g_bias_p[G4];                           // b_ih + b_hh, packed
__device__ float g_hbufT[NG * 2 * 8 * H_SZ];             // [grp][phase][j][b8] transposed h
__device__ unsigned g_cnt[NG * 2 * 32];                  // per-(group,half) arrival counters (padded)
__device__ unsigned g_gen2[NG * 2 * 32];                 // per-(group,half) generation (padded)
// bf16x3 GEMM operands
__device__ __nv_bfloat16 g_Ahi[(size_t)MROWS * I_SZ];
__device__ __nv_bfloat16 g_Alo[(size_t)MROWS * I_SZ];
__device__ __nv_bfloat16 g_Whi[G4 * I_SZ];
__device__ __nv_bfloat16 g_Wlo[G4 * I_SZ];

// ---------------- packed f32x2 helpers ----------------
__device__ __forceinline__ void ffma2(ull &d, ull a, ull b) {
    asm("fma.rn.f32x2 %0, %1, %2, %3;" : "=l"(d) : "l"(a), "l"(b), "l"(d));
}
__device__ __forceinline__ void fadd2(ull &d, ull a) {
    asm("add.rn.f32x2 %0, %1, %2;" : "=l"(d) : "l"(d), "l"(a));
}
__device__ __forceinline__ ull pack2(float x) {
    ull r; asm("mov.b64 %0, {%1, %1};" : "=l"(r) : "f"(x)); return r;
}
__device__ __forceinline__ float2 unpack2(ull v) {
    float2 r; asm("mov.b64 {%0, %1}, %2;" : "=f"(r.x), "=f"(r.y) : "l"(v)); return r;
}
__device__ __forceinline__ unsigned ld_acq(const unsigned* p) {
    unsigned v; asm volatile("ld.acquire.gpu.global.u32 %0, [%1];" : "=r"(v) : "l"(p) : "memory");
    return v;
}
__device__ __forceinline__ void st_rel(unsigned* p, unsigned v) {
    asm volatile("st.release.gpu.global.u32 [%0], %1;" :: "l"(p), "r"(v) : "memory");
}
__device__ __forceinline__ unsigned atom_add_rel(unsigned* p, unsigned v) {
    unsigned old;
    asm volatile("atom.add.release.gpu.global.u32 %0, [%1], %2;"
                 : "=r"(old) : "l"(p), "r"(v) : "memory");
    return old;
}
__device__ __forceinline__ float sigf(float x) {
    return __fdividef(1.f, 1.f + __expf(-x));
}
__device__ __forceinline__ float tanh_fast(float x) {
    float ax = fabsf(x);
    float e  = __expf(-2.f * ax);
    float r  = __fdividef(1.f - e, 1.f + e);
    return copysignf(r, x);
}

// ---------------- prep: pack/swizzle weights, transpose h0, reset sync ----------
__global__ void prep_kernel(const float* __restrict__ Wih, const float* __restrict__ Whh,
                            const float* __restrict__ bih, const float* __restrict__ bhh,
                            const float* __restrict__ h0) {
    int p = blockIdx.x;                     // packed row p = 4j + g
    int g = p & 3, j = p >> 2;
    int orig = g * H_SZ + j;

    const float* srcI = Wih + (size_t)orig * I_SZ;
    float* dI = g_wih_p + (size_t)p * I_SZ;
    for (int k = threadIdx.x; k < I_SZ; k += blockDim.x) dI[k] = srcI[k];

    const float* srcH = Whh + (size_t)orig * H_SZ;
    int cc = p >> 6, idx = p & 63, rg = idx >> 1, r = idx & 1;
    float* base = g_whh_sw + (size_t)cc * (64 * H_SZ);
    for (int k = threadIdx.x; k < H_SZ; k += blockDim.x) {
        int kq = k >> 6, rem = k & 63, kb = rem >> 2, ko = k & 3;
        int i  = kb * 2 + r, tv = kq * 32 + rg;
        base[(size_t)(i * 256 + tv) * 4 + ko] = srcH[k];
    }
    if (threadIdx.x == 0) g_bias_p[p] = bih[orig] + bhh[orig];

    if (p < H_SZ) {                          // transpose h0 -> [grp][0][j=p][b8]
        for (int b = threadIdx.x; b < B_SZ; b += blockDim.x)
            g_hbufT[(size_t)(b >> 3) * 2 * 8 * H_SZ + p * 8 + (b & 7)] = h0[(size_t)b * H_SZ + p];
    }
    if (p < NG * 2 && threadIdx.x == 0) { g_cnt[p * 32] = 0; g_gen2[p * 32] = 0; }
}

// ---------------- convert: fp32 -> bf16 hi/lo for A (input) and packed W_ih ------------
__global__ __launch_bounds__(256) void convert_kernel(const float* __restrict__ input) {
    int bid = blockIdx.x;
    const float* src;
    __nv_bfloat16 *dhi, *dlo;
    size_t i;
    if (bid < 8192) {                        // A: 32768x512 fp32
        i = ((size_t)bid * 256 + threadIdx.x) * 8;
        src = input; dhi = g_Ahi; dlo = g_Alo;
    } else {                                 // W: 2048x512 (packed)
        i = ((size_t)(bid - 8192) * 256 + threadIdx.x) * 8;
        src = g_wih_p; dhi = g_Whi; dlo = g_Wlo;
    }
    float4 x0 = *(const float4*)(src + i);
    float4 x1 = *(const float4*)(src + i + 4);
    float v[8] = {x0.x, x0.y, x0.z, x0.w, x1.x, x1.y, x1.z, x1.w};
    unsigned hs[4], ls[4];
#pragma unroll
    for (int k = 0; k < 4; k++) {
        __nv_bfloat16 h0 = __float2bfloat16(v[2 * k]);
        __nv_bfloat16 h1 = __float2bfloat16(v[2 * k + 1]);
        __nv_bfloat16 l0 = __float2bfloat16(v[2 * k]     - __bfloat162float(h0));
        __nv_bfloat16 l1 = __float2bfloat16(v[2 * k + 1] - __bfloat162float(h1));
        hs[k] = (unsigned)__bfloat16_as_ushort(h0) | ((unsigned)__bfloat16_as_ushort(h1) << 16);
        ls[k] = (unsigned)__bfloat16_as_ushort(l0) | ((unsigned)__bfloat16_as_ushort(l1) << 16);
    }
    *(uint4*)(dhi + i) = make_uint4(hs[0], hs[1], hs[2], hs[3]);
    *(uint4*)(dlo + i) = make_uint4(ls[0], ls[1], ls[2], ls[3]);
}

// ---------------- phase 1: bf16x3 HMMA GEMM -> g_gates[m][p] + bias (R10-exact) --------
#define GPITCH 40   // smem row pitch in bf16 (80B): fragment loads conflict-free

__device__ __forceinline__ void mma16816(float* c, const unsigned* a, const unsigned* b) {
    asm volatile(
        "mma.sync.aligned.m16n8k16.row.col.f32.bf16.bf16.f32 "
        "{%0,%1,%2,%3}, {%4,%5,%6,%7}, {%8,%9}, {%0,%1,%2,%3};"
        : "+f"(c[0]), "+f"(c[1]), "+f"(c[2]), "+f"(c[3])
        : "r"(a[0]), "r"(a[1]), "r"(a[2]), "r"(a[3]), "r"(b[0]), "r"(b[1]));
}

__global__ __launch_bounds__(256) void gemm_tc_kernel() {
    __shared__ __nv_bfloat16 sAh[128][GPITCH];
    __shared__ __nv_bfloat16 sAl[128][GPITCH];
    __shared__ __nv_bfloat16 sBh[128][GPITCH];
    __shared__ __nv_bfloat16 sBl[128][GPITCH];

    int tid  = threadIdx.x;
    int lane = tid & 31, wid = tid >> 5;
    int wm = wid & 3, wn = wid >> 2;            // warp tile: (wm*32, wn*64)
    int mBase = blockIdx.y * 128;
    int nBase = blockIdx.x * 128;

    int lrow = tid >> 1, lhalf = tid & 1;       // loader mapping: 128 rows x 2 halves

    float acc[2][8][4];
#pragma unroll
    for (int ma = 0; ma < 2; ma++)
#pragma unroll
        for (int na = 0; na < 8; na++)
#pragma unroll
            for (int q = 0; q < 4; q++) acc[ma][na][q] = 0.f;

    int fr = lane >> 2;                         // fragment row/col components
    int fc = (lane & 3) * 2;

    for (int ks = 0; ks < I_SZ / 32; ks++) {
        {
            size_t ga = (size_t)(mBase + lrow) * I_SZ + ks * 32 + lhalf * 16;
            const uint4* pa = (const uint4*)(g_Ahi + ga);
            uint4 a0 = __ldg(pa), a1 = __ldg(pa + 1);
            *(uint4*)&sAh[lrow][lhalf * 16]     = a0;
            *(uint4*)&sAh[lrow][lhalf * 16 + 8] = a1;
            const uint4* pl = (const uint4*)(g_Alo + ga);
            uint4 l0 = __ldg(pl), l1 = __ldg(pl + 1);
            *(uint4*)&sAl[lrow][lhalf * 16]     = l0;
            *(uint4*)&sAl[lrow][lhalf * 16 + 8] = l1;
            size_t gb = (size_t)(nBase + lrow) * I_SZ + ks * 32 + lhalf * 16;
            const uint4* pb = (const uint4*)(g_Whi + gb);
            uint4 b0 = __ldg(pb), b1 = __ldg(pb + 1);
            *(uint4*)&sBh[lrow][lhalf * 16]     = b0;
            *(uint4*)&sBh[lrow][lhalf * 16 + 8] = b1;
            const uint4* pq = (const uint4*)(g_Wlo + gb);
            uint4 q0 = __ldg(pq), q1 = __ldg(pq + 1);
            *(uint4*)&sBl[lrow][lhalf * 16]     = q0;
            *(uint4*)&sBl[lrow][lhalf * 16 + 8] = q1;
        }
        __syncthreads();

#pragma unroll
        for (int ka = 0; ka < 2; ka++) {        // two k16 atoms per chunk
            int kc = ka * 16 + fc;
            unsigned aH[2][4], aL[2][4];
#pragma unroll
            for (int ma = 0; ma < 2; ma++) {
                int r0 = wm * 32 + ma * 16 + fr;
                aH[ma][0] = *(const unsigned*)&sAh[r0][kc];
                aH[ma][1] = *(const unsigned*)&sAh[r0 + 8][kc];
                aH[ma][2] = *(const unsigned*)&sAh[r0][kc + 8];
                aH[ma][3] = *(const unsigned*)&sAh[r0 + 8][kc + 8];
                aL[ma][0] = *(const unsigned*)&sAl[r0][kc];
                aL[ma][1] = *(const unsigned*)&sAl[r0 + 8][kc];
                aL[ma][2] = *(const unsigned*)&sAl[r0][kc + 8];
                aL[ma][3] = *(const unsigned*)&sAl[r0 + 8][kc + 8];
            }
            unsigned bH[8][2], bL[8][2];
#pragma unroll
            for (int na = 0; na < 8; na++) {
                int n0 = wn * 64 + na * 8 + fr;
                bH[na][0] = *(const unsigned*)&sBh[n0][kc];
                bH[na][1] = *(const unsigned*)&sBh[n0][kc + 8];
                bL[na][0] = *(const unsigned*)&sBl[n0][kc];
                bL[na][1] = *(const unsigned*)&sBl[n0][kc + 8];
            }
#pragma unroll
            for (int ma = 0; ma < 2; ma++)
#pragma unroll
                for (int na = 0; na < 8; na++) {
                    mma16816(acc[ma][na], aH[ma], bH[na]);
                    mma16816(acc[ma][na], aH[ma], bL[na]);
                    mma16816(acc[ma][na], aL[ma], bH[na]);
                }
        }
        __syncthreads();
    }

#pragma unroll
    for (int ma = 0; ma < 2; ma++)
#pragma unroll
        for (int na = 0; na < 8; na++) {
            int row = mBase + wm * 32 + ma * 16 + fr;
            int col = nBase + wn * 64 + na * 8 + fc;
            float b0 = __ldg(&g_bias_p[col]);
            float b1 = __ldg(&g_bias_p[col + 1]);
            float* d0 = g_gates + (size_t)row * G4 + col;
            d0[0] = acc[ma][na][0] + b0;
            d0[1] = acc[ma][na][1] + b1;
            float* d1 = d0 + (size_t)8 * G4;
            d1[0] = acc[ma][na][2] + b0;
            d1[1] = acc[ma][na][3] + b1;
        }
}

// ---------------- phase 2: persistent scan (R11 + SPLIT half-barriers) ----------------
// Same compute/W-in-regs/reduction/epilogue as the 4943us R11 scan. Sync split in two:
// CTAs 0-15 of a group produce h[j<256] and arrive at (cnt,gen)_lo; CTAs 16-31 at _hi.
// Consumer warps kq<4 (threads 0-127) need only the lo half of h; threads 128-255 only
// the hi half. Each half has its own poller (tid 0 / tid 128) + named barrier, so the
// hi-half wait overlaps the lo-half's staging/compute, and each wait is a max-of-16.
__global__ __launch_bounds__(256) void scan_kernel(const float* __restrict__ c0,
                                                   float* __restrict__ out, int out_size) {
    extern __shared__ float smem[];
    float* sh_h    = smem;                          // 4096 floats (16 KB) [k][b8]
    ull*   sh_part = (ull*)(smem + 4096);           // 256*9 ull (18 KB)
    float* sh_gate = smem + 4096 + 4608;            // 64 rows * 10 floats (2.5 KB)

    int tid = threadIdx.x;
    int grp = blockIdx.x >> 5;
    int c   = blockIdx.x & 31;
    int kq  = tid >> 5;

    // W_hh slice -> REGISTERS (constant for all 1024 steps)
    float4 w4[32];
    {
        const float4* wsrc = (const float4*)(g_whh_sw + (size_t)c * (64 * H_SZ));
#pragma unroll
        for (int i = 0; i < 32; i++) w4[i] = __ldg(wsrc + tid + i * 256);
    }

    int b8 = tid >> 4, jl = tid & 15;            // epilogue mapping (tid < 128)
    float c_val = 0.f;
    const float* gxp = g_gates;
    if (tid < 128) {
        c_val = c0[(size_t)(grp * 8 + b8) * H_SZ + c * 16 + jl];
        gxp   = g_gates + (size_t)(grp * 8 + b8) * G4 + c * 64 + jl * 4;
    }
    int myhalf = c >> 4;                                      // producer half of this CTA
    unsigned* cntA   = &g_cnt [(grp * 2 + myhalf) * 32];
    unsigned* genOwn = &g_gen2[(grp * 2 + myhalf) * 32];
    unsigned* genLo  = &g_gen2[(grp * 2 + 0) * 32];
    unsigned* genHi  = &g_gen2[(grp * 2 + 1) * 32];
    float* hT0 = g_hbufT + (size_t)grp * 2 * 8 * H_SZ;

    for (int t = 0; t < T_STEPS; t++) {
        float4 gxv = make_float4(0.f, 0.f, 0.f, 0.f);
        if (tid < 128) gxv = __ldg((const float4*)(gxp + (size_t)t * B_SZ * G4));

        // ---- per-half wait + stage (lo: threads 0-127 / k<256, hi: 128-255 / k>=256) ----
        const float4* hsrc = (const float4*)(hT0 + (t & 1) * (8 * H_SZ));
        if (tid < 128) {
            if (tid == 0) { while (ld_acq(genLo) < (unsigned)t) {} }
            asm volatile("bar.sync 1, 128;" ::: "memory");
#pragma unroll
            for (int i = 0; i < 4; i++)
                ((float4*)sh_h)[tid + i * 128] = __ldcg(hsrc + tid + i * 128);
            asm volatile("bar.sync 1, 128;" ::: "memory");
        } else {
            int tl = tid - 128;
            if (tl == 0) { while (ld_acq(genHi) < (unsigned)t) {} }
            asm volatile("bar.sync 2, 128;" ::: "memory");
#pragma unroll
            for (int i = 0; i < 4; i++)
                ((float4*)sh_h)[512 + tl + i * 128] = __ldcg(hsrc + 512 + tl + i * 128);
            asm volatile("bar.sync 2, 128;" ::: "memory");
        }

        // ---- compute: identical to R11 (warps read only their own kq-eighth) ----
        ull acc[8];
#pragma unroll
        for (int i = 0; i < 8; i++) acc[i] = 0ull;

        const ulonglong2* hv = ((const ulonglong2*)sh_h) + (kq << 7);
#pragma unroll
        for (int kb = 0; kb < 16; kb++) {
            float4 w0 = w4[kb * 2 + 0];
            float4 w1 = w4[kb * 2 + 1];
            float w0a[4] = {w0.x, w0.y, w0.z, w0.w};
            float w1a[4] = {w1.x, w1.y, w1.z, w1.w};
#pragma unroll
            for (int i = 0; i < 4; i++) {
                ulonglong2 ha = hv[(kb * 4 + i) * 2 + 0];
                ulonglong2 hb = hv[(kb * 4 + i) * 2 + 1];
                ull p0 = pack2(w0a[i]), p1 = pack2(w1a[i]);
                ffma2(acc[0], ha.x, p0); ffma2(acc[1], ha.y, p0);
                ffma2(acc[2], hb.x, p0); ffma2(acc[3], hb.y, p0);
                ffma2(acc[4], ha.x, p1); ffma2(acc[5], ha.y, p1);
                ffma2(acc[6], hb.x, p1); ffma2(acc[7], hb.y, p1);
            }
        }

        if (kq != 0) {
            ull* pp = sh_part + tid * 9;
#pragma unroll
            for (int i = 0; i < 8; i++) pp[i] = acc[i];
        }
        __syncthreads();

        if (tid < 32) {
#pragma unroll
            for (int k2 = 1; k2 < 8; k2++) {
                const ull* pp = sh_part + (k2 * 32 + tid) * 9;
#pragma unroll
                for (int i = 0; i < 8; i++) fadd2(acc[i], pp[i]);
            }
            ull* g0 = (ull*)(sh_gate + (2 * tid) * 10);
            ull* g1 = (ull*)(sh_gate + (2 * tid + 1) * 10);
#pragma unroll
            for (int j = 0; j < 4; j++) { g0[j] = acc[j]; g1[j] = acc[4 + j]; }
        }
        __syncthreads();

        if (tid < 128) {
            const float* gr = sh_gate + (4 * jl) * 10 + b8;
            float pi = gr[0]  + gxv.x;
            float pf = gr[10] + gxv.y;
            float pg = gr[20] + gxv.z;
            float po = gr[30] + gxv.w;
            float ig = sigf(pi), fg = sigf(pf), og = sigf(po);
            float gg = tanh_fast(pg);
            c_val = fg * c_val + ig * gg;
            float h_new = og * tanh_fast(c_val);
            hT0[((t + 1) & 1) * (8 * H_SZ) + (c * 16 + jl) * 8 + b8] = h_new;
            out[(size_t)t * BH + (size_t)(grp * 8 + b8) * H_SZ + c * 16 + jl] = h_new;
            if (t == T_STEPS - 1 && out_size >= TBH + 2 * BH) {
                out[TBH + (grp * 8 + b8) * H_SZ + c * 16 + jl]      = h_new;  // h_f
                out[TBH + BH + (grp * 8 + b8) * H_SZ + c * 16 + jl] = c_val;  // c_f
            }
        }

        // ---- half-barrier arrival: 16 CTAs per counter ----
        __syncthreads();                      // publish visible; both pollers passed
        if (tid == 0) {
            unsigned arrived = atom_add_rel(cntA, 1u) + 1u;
            if (arrived == (unsigned)(t + 1) * (unsigned)NCH)
                st_rel(genOwn, (unsigned)(t + 1));
        }
        __syncthreads();
    }
}

// ---------------- launch ----------------
extern "C" void kernel_launch(void* const* d_in, const int* in_sizes, int n_in,
                              void* d_out, int out_size) {
    const float* input = (const float*)d_in[0];
    const float* h0    = (const float*)d_in[1];
    const float* c0    = (const float*)d_in[2];
    const float* Wih   = (const float*)d_in[3];
    const float* Whh   = (const float*)d_in[4];
    const float* bih   = (const float*)d_in[5];
    const float* bhh   = (const float*)d_in[6];
    float* out = (float*)d_out;

    prep_kernel<<<G4, 128>>>(Wih, Whh, bih, bhh, h0);
    convert_kernel<<<8192 + 512, 256>>>(input);

    dim3 gridG(G4 / 128, MROWS / 128);
    gemm_tc_kernel<<<gridG, 256>>>();

    const int scan_smem = (4096 + 4608 + 640) * (int)sizeof(float);  // 37376 B
    cudaFuncSetAttribute(scan_kernel, cudaFuncAttributeMaxDynamicSharedMemorySize, scan_smem);
    scan_kernel<<<NG * NC, 256, scan_smem>>>(c0, out, out_size);
}

// round 13
// speedup vs baseline: 4.2756x; 1.1508x over previous
#include <cuda_runtime.h>
#include <cuda_bf16.h>
#include <cstdint>

#define T_STEPS 1024
#define B_SZ    32
#define I_SZ    512
#define H_SZ    512
#define G4      2048                 // 4*H
#define TBH     (T_STEPS * B_SZ * H_SZ)
#define BH      (B_SZ * H_SZ)
#define NG      4                    // independent batch groups (8 batches each)
#define NC      32                   // CTAs per group
#define NCH     16                   // CTAs per half-barrier
#define MROWS   (T_STEPS * B_SZ)     // 32768

typedef unsigned long long ull;

// ---------------- device scratch (no allocation allowed) ----------------
__device__ float g_gates[(size_t)T_STEPS * B_SZ * G4];   // [t][b][p], p = 4j+g
__device__ float g_wih_p[G4 * I_SZ];                     // packed W_ih (p = 4j+g)
__device__ float g_bias_p[G4];                           // b_ih + b_hh, packed
__device__ float g_hbufT[NG * 2 * 8 * H_SZ];             // [grp][phase][j][b8] transposed h
__device__ unsigned g_cnt[NG * 2 * 32];                  // per-(group,half) arrival counters
__device__ unsigned g_gen2[NG * 2 * 32];                 // per-(group,half) generation
// W_hh HMMA fragments (per CTA: 16384 u32, uint4-ordered per thread)
__device__ unsigned g_wfragHi[NC * 16384];
__device__ unsigned g_wfragLo[NC * 16384];
// bf16x3 GEMM operands
__device__ __nv_bfloat16 g_Ahi[(size_t)MROWS * I_SZ];
__device__ __nv_bfloat16 g_Alo[(size_t)MROWS * I_SZ];
__device__ __nv_bfloat16 g_Whi[G4 * I_SZ];
__device__ __nv_bfloat16 g_Wlo[G4 * I_SZ];

// ---------------- helpers ----------------
__device__ __forceinline__ void fadd2(ull &d, ull a) {
    asm("add.rn.f32x2 %0, %1, %2;" : "=l"(d) : "l"(d), "l"(a));
}
__device__ __forceinline__ float2 unpack2(ull v) {
    float2 r; asm("mov.b64 {%0, %1}, %2;" : "=f"(r.x), "=f"(r.y) : "l"(v)); return r;
}
__device__ __forceinline__ ull packf2(float a, float b) {
    ull r; asm("mov.b64 %0, {%1, %2};" : "=l"(r) : "f"(a), "f"(b)); return r;
}
__device__ __forceinline__ ull pack2(float x) {
    ull r; asm("mov.b64 %0, {%1, %1};" : "=l"(r) : "f"(x)); return r;
}
__device__ __forceinline__ unsigned ld_acq(const unsigned* p) {
    unsigned v; asm volatile("ld.acquire.gpu.global.u32 %0, [%1];" : "=r"(v) : "l"(p) : "memory");
    return v;
}
__device__ __forceinline__ void st_rel(unsigned* p, unsigned v) {
    asm volatile("st.release.gpu.global.u32 [%0], %1;" :: "l"(p), "r"(v) : "memory");
}
__device__ __forceinline__ unsigned atom_add_rel(unsigned* p, unsigned v) {
    unsigned old;
    asm volatile("atom.add.release.gpu.global.u32 %0, [%1], %2;"
                 : "=r"(old) : "l"(p), "r"(v) : "memory");
    return old;
}
__device__ __forceinline__ float sigf(float x) {
    return __fdividef(1.f, 1.f + __expf(-x));
}
__device__ __forceinline__ float tanh_fast(float x) {
    float ax = fabsf(x);
    float e  = __expf(-2.f * ax);
    float r  = __fdividef(1.f - e, 1.f + e);
    return copysignf(r, x);
}
__device__ __forceinline__ void mma16816(float* c, const unsigned* a, const unsigned* b) {
    asm volatile(
        "mma.sync.aligned.m16n8k16.row.col.f32.bf16.bf16.f32 "
        "{%0,%1,%2,%3}, {%4,%5,%6,%7}, {%8,%9}, {%0,%1,%2,%3};"
        : "+f"(c[0]), "+f"(c[1]), "+f"(c[2]), "+f"(c[3])
        : "r"(a[0]), "r"(a[1]), "r"(a[2]), "r"(a[3]), "r"(b[0]), "r"(b[1]));
}
// fp32 pair -> packed bf16 hi + residual lo (low 16 bits = first element)
#define CVT2(f0, f1, HI, LO) do {                                   \
    __nv_bfloat162 _h = __floats2bfloat162_rn((f0), (f1));          \
    float _r0 = (f0) - __low2float(_h);                             \
    float _r1 = (f1) - __high2float(_h);                            \
    __nv_bfloat162 _l = __floats2bfloat162_rn(_r0, _r1);            \
    (HI) = *(unsigned*)&_h; (LO) = *(unsigned*)&_l;                 \
} while (0)

// ---------------- prep: pack W_ih, build W_hh HMMA fragments, h0, sync reset ----------
__global__ void prep_kernel(const float* __restrict__ Wih, const float* __restrict__ Whh,
                            const float* __restrict__ bih, const float* __restrict__ bhh,
                            const float* __restrict__ h0) {
    int p = blockIdx.x;                     // packed row p = 4j + g
    int g = p & 3, j = p >> 2;
    int orig = g * H_SZ + j;

    const float* srcI = Wih + (size_t)orig * I_SZ;
    float* dI = g_wih_p + (size_t)p * I_SZ;
    for (int k = threadIdx.x; k < I_SZ; k += blockDim.x) dI[k] = srcI[k];

    // W_hh -> per-thread HMMA fragment order (bf16 hi/lo).
    // CTA cc owns rows [64cc, 64cc+64); local row r: ma = r>>4, rr = r&15.
    // Fragment a-reg q: 0=(fr,kLo) 1=(fr+8,kLo) 2=(fr,kHi) 3=(fr+8,kHi);
    // lane = fr*4 + (kin&7)/2; elem = k&1. u32 idx = ((ma*4+ka)*256 + kq*32+lane)*4 + q.
    const float* srcH = Whh + (size_t)orig * H_SZ;
    int cc = p >> 6, r = p & 63;
    int ma = r >> 4, rr = r & 15;
    for (int k = threadIdx.x; k < H_SZ; k += blockDim.x) {
        float w = srcH[k];
        __nv_bfloat16 hb = __float2bfloat16(w);
        __nv_bfloat16 lb = __float2bfloat16(w - __bfloat162float(hb));
        int kq = k >> 6, ka = (k >> 4) & 3, kin = k & 15;
        int q = (rr >= 8 ? 1 : 0) + (kin >= 8 ? 2 : 0);
        int lane = (rr & 7) * 4 + ((kin & 7) >> 1);
        size_t u16idx = (((size_t)cc * 16384 + ((ma * 4 + ka) * 256 + kq * 32 + lane) * 4 + q) << 1)
                        + (k & 1);
        ((unsigned short*)g_wfragHi)[u16idx] = __bfloat16_as_ushort(hb);
        ((unsigned short*)g_wfragLo)[u16idx] = __bfloat16_as_ushort(lb);
    }
    if (threadIdx.x == 0) g_bias_p[p] = bih[orig] + bhh[orig];

    if (p < H_SZ) {                          // transpose h0 -> [grp][0][j=p][b8]
        for (int b = threadIdx.x; b < B_SZ; b += blockDim.x)
            g_hbufT[(size_t)(b >> 3) * 2 * 8 * H_SZ + p * 8 + (b & 7)] = h0[(size_t)b * H_SZ + p];
    }
    if (p < NG * 2 && threadIdx.x == 0) { g_cnt[p * 32] = 0; g_gen2[p * 32] = 0; }
}

// ---------------- convert: fp32 -> bf16 hi/lo for A (input) and packed W_ih ------------
__global__ __launch_bounds__(256) void convert_kernel(const float* __restrict__ input) {
    int bid = blockIdx.x;
    const float* src;
    __nv_bfloat16 *dhi, *dlo;
    size_t i;
    if (bid < 8192) {                        // A: 32768x512 fp32
        i = ((size_t)bid * 256 + threadIdx.x) * 8;
        src = input; dhi = g_Ahi; dlo = g_Alo;
    } else {                                 // W: 2048x512 (packed)
        i = ((size_t)(bid - 8192) * 256 + threadIdx.x) * 8;
        src = g_wih_p; dhi = g_Whi; dlo = g_Wlo;
    }
    float4 x0 = *(const float4*)(src + i);
    float4 x1 = *(const float4*)(src + i + 4);
    float v[8] = {x0.x, x0.y, x0.z, x0.w, x1.x, x1.y, x1.z, x1.w};
    unsigned hs[4], ls[4];
#pragma unroll
    for (int k = 0; k < 4; k++) CVT2(v[2 * k], v[2 * k + 1], hs[k], ls[k]);
    *(uint4*)(dhi + i) = make_uint4(hs[0], hs[1], hs[2], hs[3]);
    *(uint4*)(dlo + i) = make_uint4(ls[0], ls[1], ls[2], ls[3]);
}

// ---------------- phase 1: bf16x3 HMMA GEMM -> g_gates[m][p] + bias (R10-exact) --------
#define GPITCH 40   // smem row pitch in bf16 (80B): fragment loads conflict-free

__global__ __launch_bounds__(256) void gemm_tc_kernel() {
    __shared__ __nv_bfloat16 sAh[128][GPITCH];
    __shared__ __nv_bfloat16 sAl[128][GPITCH];
    __shared__ __nv_bfloat16 sBh[128][GPITCH];
    __shared__ __nv_bfloat16 sBl[128][GPITCH];

    int tid  = threadIdx.x;
    int lane = tid & 31, wid = tid >> 5;
    int wm = wid & 3, wn = wid >> 2;            // warp tile: (wm*32, wn*64)
    int mBase = blockIdx.y * 128;
    int nBase = blockIdx.x * 128;

    int lrow = tid >> 1, lhalf = tid & 1;

    float acc[2][8][4];
#pragma unroll
    for (int ma = 0; ma < 2; ma++)
#pragma unroll
        for (int na = 0; na < 8; na++)
#pragma unroll
            for (int q = 0; q < 4; q++) acc[ma][na][q] = 0.f;

    int fr = lane >> 2;
    int fc = (lane & 3) * 2;

    for (int ks = 0; ks < I_SZ / 32; ks++) {
        {
            size_t ga = (size_t)(mBase + lrow) * I_SZ + ks * 32 + lhalf * 16;
            const uint4* pa = (const uint4*)(g_Ahi + ga);
            uint4 a0 = __ldg(pa), a1 = __ldg(pa + 1);
            *(uint4*)&sAh[lrow][lhalf * 16]     = a0;
            *(uint4*)&sAh[lrow][lhalf * 16 + 8] = a1;
            const uint4* pl = (const uint4*)(g_Alo + ga);
            uint4 l0 = __ldg(pl), l1 = __ldg(pl + 1);
            *(uint4*)&sAl[lrow][lhalf * 16]     = l0;
            *(uint4*)&sAl[lrow][lhalf * 16 + 8] = l1;
            size_t gb = (size_t)(nBase + lrow) * I_SZ + ks * 32 + lhalf * 16;
            const uint4* pb = (const uint4*)(g_Whi + gb);
            uint4 b0 = __ldg(pb), b1 = __ldg(pb + 1);
            *(uint4*)&sBh[lrow][lhalf * 16]     = b0;
            *(uint4*)&sBh[lrow][lhalf * 16 + 8] = b1;
            const uint4* pq = (const uint4*)(g_Wlo + gb);
            uint4 q0 = __ldg(pq), q1 = __ldg(pq + 1);
            *(uint4*)&sBl[lrow][lhalf * 16]     = q0;
            *(uint4*)&sBl[lrow][lhalf * 16 + 8] = q1;
        }
        __syncthreads();

#pragma unroll
        for (int ka = 0; ka < 2; ka++) {
            int kc = ka * 16 + fc;
            unsigned aH[2][4], aL[2][4];
#pragma unroll
            for (int ma = 0; ma < 2; ma++) {
                int r0 = wm * 32 + ma * 16 + fr;
                aH[ma][0] = *(const unsigned*)&sAh[r0][kc];
                aH[ma][1] = *(const unsigned*)&sAh[r0 + 8][kc];
                aH[ma][2] = *(const unsigned*)&sAh[r0][kc + 8];
                aH[ma][3] = *(const unsigned*)&sAh[r0 + 8][kc + 8];
                aL[ma][0] = *(const unsigned*)&sAl[r0][kc];
                aL[ma][1] = *(const unsigned*)&sAl[r0 + 8][kc];
                aL[ma][2] = *(const unsigned*)&sAl[r0][kc + 8];
                aL[ma][3] = *(const unsigned*)&sAl[r0 + 8][kc + 8];
            }
            unsigned bH[8][2], bL[8][2];
#pragma unroll
            for (int na = 0; na < 8; na++) {
                int n0 = wn * 64 + na * 8 + fr;
                bH[na][0] = *(const unsigned*)&sBh[n0][kc];
                bH[na][1] = *(const unsigned*)&sBh[n0][kc + 8];
                bL[na][0] = *(const unsigned*)&sBl[n0][kc];
                bL[na][1] = *(const unsigned*)&sBl[n0][kc + 8];
            }
#pragma unroll
            for (int ma = 0; ma < 2; ma++)
#pragma unroll
                for (int na = 0; na < 8; na++) {
                    mma16816(acc[ma][na], aH[ma], bH[na]);
                    mma16816(acc[ma][na], aH[ma], bL[na]);
                    mma16816(acc[ma][na], aL[ma], bH[na]);
                }
        }
        __syncthreads();
    }

#pragma unroll
    for (int ma = 0; ma < 2; ma++)
#pragma unroll
        for (int na = 0; na < 8; na++) {
            int row = mBase + wm * 32 + ma * 16 + fr;
            int col = nBase + wn * 64 + na * 8 + fc;
            float b0 = __ldg(&g_bias_p[col]);
            float b1 = __ldg(&g_bias_p[col + 1]);
            float* d0 = g_gates + (size_t)row * G4 + col;
            d0[0] = acc[ma][na][0] + b0;
            d0[1] = acc[ma][na][1] + b1;
            float* d1 = d0 + (size_t)8 * G4;
            d1[0] = acc[ma][na][2] + b0;
            d1[1] = acc[ma][na][3] + b1;
        }
}

// ---------------- phase 2: persistent scan (R12 sync + HMMA bf16x3 compute) ------------
// Sync/staging/epilogue byte-identical to R12. Compute: warp kq does its K-64 chunk via
// 48 mma.m16n8k16 (4 m-atoms x 4 k-atoms x 3 bf16x3 passes), W fragments preloaded in
// registers, h converted per-warp to packed bf16 hi/lo in smem. Reduction parallelized.
__global__ __launch_bounds__(256) void scan_kernel(const float* __restrict__ c0,
                                                   float* __restrict__ out, int out_size) {
    extern __shared__ float smem[];
    float*    sh_h  = smem;                        // 4096 f (16 KB) [k][b8] fp32
    unsigned* shHi  = (unsigned*)(smem + 4096);    // 2048 u32: [k2][b8] packed bf16 hi
    unsigned* shLo  = (unsigned*)(smem + 6144);    // 2048 u32
    ull*      sh_part = (ull*)(smem + 8192);       // 256*9 ull (18 KB)
    float*    sh_gate = smem + 8192 + 4608;        // 64 rows * 10 floats

    int tid = threadIdx.x;
    int grp = blockIdx.x >> 5;
    int c   = blockIdx.x & 31;
    int lane = tid & 31, kq = tid >> 5;

    // W_hh fragments -> registers (constant for all 1024 steps)
    uint4 wHi[16], wLo[16];
    {
        const uint4* fh = ((const uint4*)g_wfragHi) + c * 4096;
        const uint4* fl = ((const uint4*)g_wfragLo) + c * 4096;
#pragma unroll
        for (int i = 0; i < 16; i++) {
            wHi[i] = __ldg(fh + i * 256 + tid);
            wLo[i] = __ldg(fl + i * 256 + tid);
        }
    }

    int b8 = tid >> 4, jl = tid & 15;            // epilogue mapping (tid < 128)
    float c_val = 0.f;
    const float* gxp = g_gates;
    if (tid < 128) {
        c_val = c0[(size_t)(grp * 8 + b8) * H_SZ + c * 16 + jl];
        gxp   = g_gates + (size_t)(grp * 8 + b8) * G4 + c * 64 + jl * 4;
    }
    int myhalf = c >> 4;
    unsigned* cntA   = &g_cnt [(grp * 2 + myhalf) * 32];
    unsigned* genOwn = &g_gen2[(grp * 2 + myhalf) * 32];
    unsigned* genLo  = &g_gen2[(grp * 2 + 0) * 32];
    unsigned* genHi  = &g_gen2[(grp * 2 + 1) * 32];
    float* hT0 = g_hbufT + (size_t)grp * 2 * 8 * H_SZ;

    for (int t = 0; t < T_STEPS; t++) {
        float4 gxv = make_float4(0.f, 0.f, 0.f, 0.f);
        if (tid < 128) gxv = __ldg((const float4*)(gxp + (size_t)t * B_SZ * G4));

        // ---- per-half wait + stage (identical to R12) ----
        const float4* hsrc = (const float4*)(hT0 + (t & 1) * (8 * H_SZ));
        if (tid < 128) {
            if (tid == 0) { while (ld_acq(genLo) < (unsigned)t) {} }
            asm volatile("bar.sync 1, 128;" ::: "memory");
#pragma unroll
            for (int i = 0; i < 4; i++)
                ((float4*)sh_h)[tid + i * 128] = __ldcg(hsrc + tid + i * 128);
            asm volatile("bar.sync 1, 128;" ::: "memory");
        } else {
            int tl = tid - 128;
            if (tl == 0) { while (ld_acq(genHi) < (unsigned)t) {} }
            asm volatile("bar.sync 2, 128;" ::: "memory");
#pragma unroll
            for (int i = 0; i < 4; i++)
                ((float4*)sh_h)[512 + tl + i * 128] = __ldcg(hsrc + 512 + tl + i * 128);
            asm volatile("bar.sync 2, 128;" ::: "memory");
        }

        // ---- convert own k2 = tid (rows 2tid, 2tid+1) to packed bf16 hi/lo ----
        {
            const float4* s4 = (const float4*)sh_h;
            float4 r0a = s4[4 * tid], r0b = s4[4 * tid + 1];
            float4 r1a = s4[4 * tid + 2], r1b = s4[4 * tid + 3];
            unsigned hi[8], lo[8];
            CVT2(r0a.x, r1a.x, hi[0], lo[0]); CVT2(r0a.y, r1a.y, hi[1], lo[1]);
            CVT2(r0a.z, r1a.z, hi[2], lo[2]); CVT2(r0a.w, r1a.w, hi[3], lo[3]);
            CVT2(r0b.x, r1b.x, hi[4], lo[4]); CVT2(r0b.y, r1b.y, hi[5], lo[5]);
            CVT2(r0b.z, r1b.z, hi[6], lo[6]); CVT2(r0b.w, r1b.w, hi[7], lo[7]);
            ((uint4*)shHi)[2 * tid]     = make_uint4(hi[0], hi[1], hi[2], hi[3]);
            ((uint4*)shHi)[2 * tid + 1] = make_uint4(hi[4], hi[5], hi[6], hi[7]);
            ((uint4*)shLo)[2 * tid]     = make_uint4(lo[0], lo[1], lo[2], lo[3]);
            ((uint4*)shLo)[2 * tid + 1] = make_uint4(lo[4], lo[5], lo[6], lo[7]);
        }
        __syncwarp();          // warp kq reads only k2 in [32kq, 32kq+32) — own warp's writes

        // ---- HMMA bf16x3: 4 m-atoms x 4 k-atoms x 3 passes ----
        float acc[4][4];
#pragma unroll
        for (int ma = 0; ma < 4; ma++)
#pragma unroll
            for (int q = 0; q < 4; q++) acc[ma][q] = 0.f;

        int n = lane >> 2;
#pragma unroll
        for (int ka = 0; ka < 4; ka++) {
            int k2b = kq * 32 + ka * 8 + (lane & 3);
            unsigned bh[2] = { shHi[k2b * 8 + n], shHi[(k2b + 4) * 8 + n] };
            unsigned bl[2] = { shLo[k2b * 8 + n], shLo[(k2b + 4) * 8 + n] };
#pragma unroll
            for (int ma = 0; ma < 4; ma++) {
                const unsigned* aH = (const unsigned*)&wHi[ma * 4 + ka];
                const unsigned* aL = (const unsigned*)&wLo[ma * 4 + ka];
                mma16816(acc[ma], aH, bh);
                mma16816(acc[ma], aH, bl);
                mma16816(acc[ma], aL, bh);
            }
        }

        // ---- dump ALL partials, parallel cross-kq reduce ----
        {
            ull* pp = sh_part + tid * 9;
#pragma unroll
            for (int ma = 0; ma < 4; ma++) {
                pp[ma * 2]     = packf2(acc[ma][0], acc[ma][1]);
                pp[ma * 2 + 1] = packf2(acc[ma][2], acc[ma][3]);
            }
        }
        __syncthreads();
        {
            int l = tid & 31, s = tid >> 5;          // one (lane, slot) per thread
            ull v = sh_part[l * 9 + s];
#pragma unroll
            for (int k2 = 1; k2 < 8; k2++) fadd2(v, sh_part[((k2 << 5) + l) * 9 + s]);
            float2 vf = unpack2(v);
            int ma = s >> 1, half = s & 1;
            int row  = ma * 16 + (l >> 2) + 8 * half;
            int bcol = (l & 3) * 2;
            sh_gate[row * 10 + bcol]     = vf.x;
            sh_gate[row * 10 + bcol + 1] = vf.y;
        }
        __syncthreads();

        // ---- epilogue (identical to R12) ----
        if (tid < 128) {
            const float* gr = sh_gate + (4 * jl) * 10 + b8;
            float pi = gr[0]  + gxv.x;
            float pf = gr[10] + gxv.y;
            float pg = gr[20] + gxv.z;
            float po = gr[30] + gxv.w;
            float ig = sigf(pi), fg = sigf(pf), og = sigf(po);
            float gg = tanh_fast(pg);
            c_val = fg * c_val + ig * gg;
            float h_new = og * tanh_fast(c_val);
            hT0[((t + 1) & 1) * (8 * H_SZ) + (c * 16 + jl) * 8 + b8] = h_new;
            out[(size_t)t * BH + (size_t)(grp * 8 + b8) * H_SZ + c * 16 + jl] = h_new;
            if (t == T_STEPS - 1 && out_size >= TBH + 2 * BH) {
                out[TBH + (grp * 8 + b8) * H_SZ + c * 16 + jl]      = h_new;  // h_f
                out[TBH + BH + (grp * 8 + b8) * H_SZ + c * 16 + jl] = c_val;  // c_f
            }
        }

        // ---- half-barrier arrival (identical to R12) ----
        __syncthreads();
        if (tid == 0) {
            unsigned arrived = atom_add_rel(cntA, 1u) + 1u;
            if (arrived == (unsigned)(t + 1) * (unsigned)NCH)
                st_rel(genOwn, (unsigned)(t + 1));
        }
        __syncthreads();
    }
}

// ---------------- launch ----------------
extern "C" void kernel_launch(void* const* d_in, const int* in_sizes, int n_in,
                              void* d_out, int out_size) {
    const float* input = (const float*)d_in[0];
    const float* h0    = (const float*)d_in[1];
    const float* c0    = (const float*)d_in[2];
    const float* Wih   = (const float*)d_in[3];
    const float* Whh   = (const float*)d_in[4];
    const float* bih   = (const float*)d_in[5];
    const float* bhh   = (const float*)d_in[6];
    float* out = (float*)d_out;

    prep_kernel<<<G4, 128>>>(Wih, Whh, bih, bhh, h0);
    convert_kernel<<<8192 + 512, 256>>>(input);

    dim3 gridG(G4 / 128, MROWS / 128);
    gemm_tc_kernel<<<gridG, 256>>>();

    const int scan_smem = (8192 + 4608 + 640) * (int)sizeof(float);  // 53760 B
    cudaFuncSetAttribute(scan_kernel, cudaFuncAttributeMaxDynamicSharedMemorySize, scan_smem);
    scan_kernel<<<NG * NC, 256, scan_smem>>>(c0, out, out_size);
}

// round 14
// speedup vs baseline: 4.6897x; 1.0969x over previous
#include <cuda_runtime.h>
#include <cuda_bf16.h>
#include <cstdint>

#define T_STEPS 1024
#define B_SZ    32
#define I_SZ    512
#define H_SZ    512
#define G4      2048                 // 4*H
#define TBH     (T_STEPS * B_SZ * H_SZ)
#define BH      (B_SZ * H_SZ)
#define NG      4                    // independent batch groups (8 batches each)
#define NC      32                   // CTAs per group
#define NCH     16                   // CTAs per half-barrier
#define MROWS   (T_STEPS * B_SZ)     // 32768

typedef unsigned long long ull;

// ---------------- device scratch (no allocation allowed) ----------------
__device__ float g_gates[(size_t)T_STEPS * B_SZ * G4];   // [t][b][p], p = 4j+g
__device__ float g_wih_p[G4 * I_SZ];                     // packed W_ih (p = 4j+g)
__device__ float g_bias_p[G4];                           // b_ih + b_hh, packed
__device__ unsigned g_hpkHi[NG * 2 * 2048];              // [grp][ph][k2][b8] bf16x2 hi
__device__ unsigned g_hpkLo[NG * 2 * 2048];              // [grp][ph][k2][b8] bf16x2 lo
__device__ unsigned g_cnt[NG * 2 * 32];                  // per-(group,half) arrival counters
__device__ unsigned g_gen2[NG * 2 * 32];                 // per-(group,half) generation
// W_hh HMMA fragments (per CTA: 16384 u32, uint4-ordered per thread)
__device__ unsigned g_wfragHi[NC * 16384];
__device__ unsigned g_wfragLo[NC * 16384];
// bf16x3 GEMM operands
__device__ __nv_bfloat16 g_Ahi[(size_t)MROWS * I_SZ];
__device__ __nv_bfloat16 g_Alo[(size_t)MROWS * I_SZ];
__device__ __nv_bfloat16 g_Whi[G4 * I_SZ];
__device__ __nv_bfloat16 g_Wlo[G4 * I_SZ];

// ---------------- helpers ----------------
__device__ __forceinline__ void fadd2(ull &d, ull a) {
    asm("add.rn.f32x2 %0, %1, %2;" : "=l"(d) : "l"(d), "l"(a));
}
__device__ __forceinline__ float2 unpack2(ull v) {
    float2 r; asm("mov.b64 {%0, %1}, %2;" : "=f"(r.x), "=f"(r.y) : "l"(v)); return r;
}
__device__ __forceinline__ ull packf2(float a, float b) {
    ull r; asm("mov.b64 %0, {%1, %2};" : "=l"(r) : "f"(a), "f"(b)); return r;
}
__device__ __forceinline__ unsigned ld_acq(const unsigned* p) {
    unsigned v; asm volatile("ld.acquire.gpu.global.u32 %0, [%1];" : "=r"(v) : "l"(p) : "memory");
    return v;
}
__device__ __forceinline__ void st_rel(unsigned* p, unsigned v) {
    asm volatile("st.release.gpu.global.u32 [%0], %1;" :: "l"(p), "r"(v) : "memory");
}
__device__ __forceinline__ unsigned atom_add_rel(unsigned* p, unsigned v) {
    unsigned old;
    asm volatile("atom.add.release.gpu.global.u32 %0, [%1], %2;"
                 : "=r"(old) : "l"(p), "r"(v) : "memory");
    return old;
}
__device__ __forceinline__ float sigf(float x) {
    return __fdividef(1.f, 1.f + __expf(-x));
}
__device__ __forceinline__ float tanh_fast(float x) {
    float ax = fabsf(x);
    float e  = __expf(-2.f * ax);
    float r  = __fdividef(1.f - e, 1.f + e);
    return copysignf(r, x);
}
__device__ __forceinline__ void mma16816(float* c, const unsigned* a, const unsigned* b) {
    asm volatile(
        "mma.sync.aligned.m16n8k16.row.col.f32.bf16.bf16.f32 "
        "{%0,%1,%2,%3}, {%4,%5,%6,%7}, {%8,%9}, {%0,%1,%2,%3};"
        : "+f"(c[0]), "+f"(c[1]), "+f"(c[2]), "+f"(c[3])
        : "r"(a[0]), "r"(a[1]), "r"(a[2]), "r"(a[3]), "r"(b[0]), "r"(b[1]));
}
// fp32 pair -> packed bf16 hi + residual lo (low 16 bits = first element)
#define CVT2(f0, f1, HI, LO) do {                                   \
    __nv_bfloat162 _h = __floats2bfloat162_rn((f0), (f1));          \
    float _r0 = (f0) - __low2float(_h);                             \
    float _r1 = (f1) - __high2float(_h);                            \
    __nv_bfloat162 _l = __floats2bfloat162_rn(_r0, _r1);            \
    (HI) = *(unsigned*)&_h; (LO) = *(unsigned*)&_l;                 \
} while (0)

// ---------------- prep: pack W_ih, W_hh fragments, packed h0, sync reset ----------
__global__ void prep_kernel(const float* __restrict__ Wih, const float* __restrict__ Whh,
                            const float* __restrict__ bih, const float* __restrict__ bhh,
                            const float* __restrict__ h0) {
    int p = blockIdx.x;                     // packed row p = 4j + g
    int g = p & 3, j = p >> 2;
    int orig = g * H_SZ + j;

    const float* srcI = Wih + (size_t)orig * I_SZ;
    float* dI = g_wih_p + (size_t)p * I_SZ;
    for (int k = threadIdx.x; k < I_SZ; k += blockDim.x) dI[k] = srcI[k];

    // W_hh -> per-thread HMMA fragment order (bf16 hi/lo).  (same as R13)
    const float* srcH = Whh + (size_t)orig * H_SZ;
    int cc = p >> 6, r = p & 63;
    int ma = r >> 4, rr = r & 15;
    for (int k = threadIdx.x; k < H_SZ; k += blockDim.x) {
        float w = srcH[k];
        __nv_bfloat16 hb = __float2bfloat16(w);
        __nv_bfloat16 lb = __float2bfloat16(w - __bfloat162float(hb));
        int kq = k >> 6, ka = (k >> 4) & 3, kin = k & 15;
        int q = (rr >= 8 ? 1 : 0) + (kin >= 8 ? 2 : 0);
        int lane = (rr & 7) * 4 + ((kin & 7) >> 1);
        size_t u16idx = (((size_t)cc * 16384 + ((ma * 4 + ka) * 256 + kq * 32 + lane) * 4 + q) << 1)
                        + (k & 1);
        ((unsigned short*)g_wfragHi)[u16idx] = __bfloat16_as_ushort(hb);
        ((unsigned short*)g_wfragLo)[u16idx] = __bfloat16_as_ushort(lb);
    }
    if (threadIdx.x == 0) g_bias_p[p] = bih[orig] + bhh[orig];

    // h0 -> packed bf16 hi/lo pairs, consumer layout [grp][0][k2][b8]
    if (p < H_SZ && !(p & 1)) {
        for (int b = threadIdx.x; b < B_SZ; b += blockDim.x) {
            unsigned hi, lo;
            CVT2(h0[(size_t)b * H_SZ + p], h0[(size_t)b * H_SZ + p + 1], hi, lo);
            int idx = (b >> 3) * 2 * 2048 + (p >> 1) * 8 + (b & 7);
            g_hpkHi[idx] = hi; g_hpkLo[idx] = lo;
        }
    }
    if (p < NG * 2 && threadIdx.x == 0) { g_cnt[p * 32] = 0; g_gen2[p * 32] = 0; }
}

// ---------------- convert: fp32 -> bf16 hi/lo for A (input) and packed W_ih ------------
__global__ __launch_bounds__(256) void convert_kernel(const float* __restrict__ input) {
    int bid = blockIdx.x;
    const float* src;
    __nv_bfloat16 *dhi, *dlo;
    size_t i;
    if (bid < 8192) {                        // A: 32768x512 fp32
        i = ((size_t)bid * 256 + threadIdx.x) * 8;
        src = input; dhi = g_Ahi; dlo = g_Alo;
    } else {                                 // W: 2048x512 (packed)
        i = ((size_t)(bid - 8192) * 256 + threadIdx.x) * 8;
        src = g_wih_p; dhi = g_Whi; dlo = g_Wlo;
    }
    float4 x0 = *(const float4*)(src + i);
    float4 x1 = *(const float4*)(src + i + 4);
    float v[8] = {x0.x, x0.y, x0.z, x0.w, x1.x, x1.y, x1.z, x1.w};
    unsigned hs[4], ls[4];
#pragma unroll
    for (int k = 0; k < 4; k++) CVT2(v[2 * k], v[2 * k + 1], hs[k], ls[k]);
    *(uint4*)(dhi + i) = make_uint4(hs[0], hs[1], hs[2], hs[3]);
    *(uint4*)(dlo + i) = make_uint4(ls[0], ls[1], ls[2], ls[3]);
}

// ---------------- phase 1: bf16x3 HMMA GEMM, register double-buffered ----------------
#define GPITCH 40   // smem row pitch in bf16 (80B): fragment loads conflict-free

__global__ __launch_bounds__(256) void gemm_tc_kernel() {
    __shared__ __nv_bfloat16 sAh[128][GPITCH];
    __shared__ __nv_bfloat16 sAl[128][GPITCH];
    __shared__ __nv_bfloat16 sBh[128][GPITCH];
    __shared__ __nv_bfloat16 sBl[128][GPITCH];

    int tid  = threadIdx.x;
    int lane = tid & 31, wid = tid >> 5;
    int wm = wid & 3, wn = wid >> 2;            // warp tile: (wm*32, wn*64)
    int mBase = blockIdx.y * 128;
    int nBase = blockIdx.x * 128;

    int lrow = tid >> 1, lhalf = tid & 1;

    float acc[2][8][4];
#pragma unroll
    for (int ma = 0; ma < 2; ma++)
#pragma unroll
        for (int na = 0; na < 8; na++)
#pragma unroll
            for (int q = 0; q < 4; q++) acc[ma][na][q] = 0.f;

    int fr = lane >> 2;
    int fc = (lane & 3) * 2;

    size_t gaRow = (size_t)(mBase + lrow) * I_SZ + lhalf * 16;
    size_t gbRow = (size_t)(nBase + lrow) * I_SZ + lhalf * 16;
    // register prefetch of chunk 0
    uint4 ra0 = __ldg((const uint4*)(g_Ahi + gaRow));
    uint4 ra1 = __ldg((const uint4*)(g_Ahi + gaRow) + 1);
    uint4 rl0 = __ldg((const uint4*)(g_Alo + gaRow));
    uint4 rl1 = __ldg((const uint4*)(g_Alo + gaRow) + 1);
    uint4 rb0 = __ldg((const uint4*)(g_Whi + gbRow));
    uint4 rb1 = __ldg((const uint4*)(g_Whi + gbRow) + 1);
    uint4 rq0 = __ldg((const uint4*)(g_Wlo + gbRow));
    uint4 rq1 = __ldg((const uint4*)(g_Wlo + gbRow) + 1);

    for (int ks = 0; ks < I_SZ / 32; ks++) {
        *(uint4*)&sAh[lrow][lhalf * 16]     = ra0;
        *(uint4*)&sAh[lrow][lhalf * 16 + 8] = ra1;
        *(uint4*)&sAl[lrow][lhalf * 16]     = rl0;
        *(uint4*)&sAl[lrow][lhalf * 16 + 8] = rl1;
        *(uint4*)&sBh[lrow][lhalf * 16]     = rb0;
        *(uint4*)&sBh[lrow][lhalf * 16 + 8] = rb1;
        *(uint4*)&sBl[lrow][lhalf * 16]     = rq0;
        *(uint4*)&sBl[lrow][lhalf * 16 + 8] = rq1;
        __syncthreads();

        if (ks + 1 < I_SZ / 32) {               // prefetch next chunk while computing
            size_t ga = gaRow + (ks + 1) * 32;
            size_t gb = gbRow + (ks + 1) * 32;
            ra0 = __ldg((const uint4*)(g_Ahi + ga));
            ra1 = __ldg((const uint4*)(g_Ahi + ga) + 1);
            rl0 = __ldg((const uint4*)(g_Alo + ga));
            rl1 = __ldg((const uint4*)(g_Alo + ga) + 1);
            rb0 = __ldg((const uint4*)(g_Whi + gb));
            rb1 = __ldg((const uint4*)(g_Whi + gb) + 1);
            rq0 = __ldg((const uint4*)(g_Wlo + gb));
            rq1 = __ldg((const uint4*)(g_Wlo + gb) + 1);
        }

#pragma unroll
        for (int ka = 0; ka < 2; ka++) {
            int kc = ka * 16 + fc;
            unsigned aH[2][4], aL[2][4];
#pragma unroll
            for (int ma = 0; ma < 2; ma++) {
                int r0 = wm * 32 + ma * 16 + fr;
                aH[ma][0] = *(const unsigned*)&sAh[r0][kc];
                aH[ma][1] = *(const unsigned*)&sAh[r0 + 8][kc];
                aH[ma][2] = *(const unsigned*)&sAh[r0][kc + 8];
                aH[ma][3] = *(const unsigned*)&sAh[r0 + 8][kc + 8];
                aL[ma][0] = *(const unsigned*)&sAl[r0][kc];
                aL[ma][1] = *(const unsigned*)&sAl[r0 + 8][kc];
                aL[ma][2] = *(const unsigned*)&sAl[r0][kc + 8];
                aL[ma][3] = *(const unsigned*)&sAl[r0 + 8][kc + 8];
            }
            unsigned bH[8][2], bL[8][2];
#pragma unroll
            for (int na = 0; na < 8; na++) {
                int n0 = wn * 64 + na * 8 + fr;
                bH[na][0] = *(const unsigned*)&sBh[n0][kc];
                bH[na][1] = *(const unsigned*)&sBh[n0][kc + 8];
                bL[na][0] = *(const unsigned*)&sBl[n0][kc];
                bL[na][1] = *(const unsigned*)&sBl[n0][kc + 8];
            }
#pragma unroll
            for (int ma = 0; ma < 2; ma++)
#pragma unroll
                for (int na = 0; na < 8; na++) {
                    mma16816(acc[ma][na], aH[ma], bH[na]);
                    mma16816(acc[ma][na], aH[ma], bL[na]);
                    mma16816(acc[ma][na], aL[ma], bH[na]);
                }
        }
        __syncthreads();
    }

#pragma unroll
    for (int ma = 0; ma < 2; ma++)
#pragma unroll
        for (int na = 0; na < 8; na++) {
            int row = mBase + wm * 32 + ma * 16 + fr;
            int col = nBase + wn * 64 + na * 8 + fc;
            float b0 = __ldg(&g_bias_p[col]);
            float b1 = __ldg(&g_bias_p[col + 1]);
            float* d0 = g_gates + (size_t)row * G4 + col;
            d0[0] = acc[ma][na][0] + b0;
            d0[1] = acc[ma][na][1] + b1;
            float* d1 = d0 + (size_t)8 * G4;
            d1[0] = acc[ma][na][2] + b0;
            d1[1] = acc[ma][na][3] + b1;
        }
}

// ---------------- phase 2: persistent scan (R13 + producer-side packing) ---------------
// Producers publish h as packed bf16 hi/lo pairs in MMA b-fragment layout [k2][b8];
// consumers stage those u32 arrays directly (no per-step conversion). out[] stores
// moved after the arrival atomic; trailing __syncthreads removed.
__global__ __launch_bounds__(256) void scan_kernel(const float* __restrict__ c0,
                                                   float* __restrict__ out, int out_size) {
    extern __shared__ float smem[];
    unsigned* shHi  = (unsigned*)smem;             // 2048 u32: [k2][b8] bf16x2 hi
    unsigned* shLo  = (unsigned*)(smem + 2048);    // 2048 u32
    ull*      sh_part = (ull*)(smem + 4096);       // 256*9 ull (18 KB)
    float*    sh_gate = smem + 4096 + 4608;        // 64 rows * 10 floats

    int tid = threadIdx.x;
    int grp = blockIdx.x >> 5;
    int c   = blockIdx.x & 31;
    int lane = tid & 31, kq = tid >> 5;

    // W_hh fragments -> registers (constant for all 1024 steps)
    uint4 wHi[16], wLo[16];
    {
        const uint4* fh = ((const uint4*)g_wfragHi) + c * 4096;
        const uint4* fl = ((const uint4*)g_wfragLo) + c * 4096;
#pragma unroll
        for (int i = 0; i < 16; i++) {
            wHi[i] = __ldg(fh + i * 256 + tid);
            wLo[i] = __ldg(fl + i * 256 + tid);
        }
    }

    int b8 = tid >> 4, jl = tid & 15;            // epilogue mapping (tid < 128)
    float c_val = 0.f;
    const float* gxp = g_gates;
    if (tid < 128) {
        c_val = c0[(size_t)(grp * 8 + b8) * H_SZ + c * 16 + jl];
        gxp   = g_gates + (size_t)(grp * 8 + b8) * G4 + c * 64 + jl * 4;
    }
    int myhalf = c >> 4;
    unsigned* cntA   = &g_cnt [(grp * 2 + myhalf) * 32];
    unsigned* genOwn = &g_gen2[(grp * 2 + myhalf) * 32];
    unsigned* genLo  = &g_gen2[(grp * 2 + 0) * 32];
    unsigned* genHi  = &g_gen2[(grp * 2 + 1) * 32];
    unsigned* gHi = g_hpkHi + grp * 2 * 2048;
    unsigned* gLo = g_hpkLo + grp * 2 * 2048;

    for (int t = 0; t < T_STEPS; t++) {
        float4 gxv = make_float4(0.f, 0.f, 0.f, 0.f);
        if (tid < 128) gxv = __ldg((const float4*)(gxp + (size_t)t * B_SZ * G4));

        // ---- per-half wait + stage packed hi/lo directly ----
        const uint4* hHi4 = (const uint4*)(gHi + (t & 1) * 2048);
        const uint4* hLo4 = (const uint4*)(gLo + (t & 1) * 2048);
        if (tid < 128) {
            if (tid == 0) { while (ld_acq(genLo) < (unsigned)t) {} }
            asm volatile("bar.sync 1, 128;" ::: "memory");
            ((uint4*)shHi)[tid]       = __ldcg(hHi4 + tid);
            ((uint4*)shHi)[tid + 128] = __ldcg(hHi4 + tid + 128);
            ((uint4*)shLo)[tid]       = __ldcg(hLo4 + tid);
            ((uint4*)shLo)[tid + 128] = __ldcg(hLo4 + tid + 128);
            asm volatile("bar.sync 1, 128;" ::: "memory");
        } else {
            int tl = tid - 128;
            if (tl == 0) { while (ld_acq(genHi) < (unsigned)t) {} }
            asm volatile("bar.sync 2, 128;" ::: "memory");
            ((uint4*)shHi)[256 + tl] = __ldcg(hHi4 + 256 + tl);
            ((uint4*)shHi)[384 + tl] = __ldcg(hHi4 + 384 + tl);
            ((uint4*)shLo)[256 + tl] = __ldcg(hLo4 + 256 + tl);
            ((uint4*)shLo)[384 + tl] = __ldcg(hLo4 + 384 + tl);
            asm volatile("bar.sync 2, 128;" ::: "memory");
        }

        // ---- HMMA bf16x3: 4 m-atoms x 4 k-atoms x 3 passes ----
        float acc[4][4];
#pragma unroll
        for (int ma = 0; ma < 4; ma++)
#pragma unroll
            for (int q = 0; q < 4; q++) acc[ma][q] = 0.f;

        int n = lane >> 2;
#pragma unroll
        for (int ka = 0; ka < 4; ka++) {
            int k2b = kq * 32 + ka * 8 + (lane & 3);
            unsigned bh[2] = { shHi[k2b * 8 + n], shHi[(k2b + 4) * 8 + n] };
            unsigned bl[2] = { shLo[k2b * 8 + n], shLo[(k2b + 4) * 8 + n] };
#pragma unroll
            for (int ma = 0; ma < 4; ma++) {
                const unsigned* aH = (const unsigned*)&wHi[ma * 4 + ka];
                const unsigned* aL = (const unsigned*)&wLo[ma * 4 + ka];
                mma16816(acc[ma], aH, bh);
                mma16816(acc[ma], aH, bl);
                mma16816(acc[ma], aL, bh);
            }
        }

        // ---- dump partials, parallel cross-kq reduce ----
        {
            ull* pp = sh_part + tid * 9;
#pragma unroll
            for (int ma = 0; ma < 4; ma++) {
                pp[ma * 2]     = packf2(acc[ma][0], acc[ma][1]);
                pp[ma * 2 + 1] = packf2(acc[ma][2], acc[ma][3]);
            }
        }
        __syncthreads();
        {
            int l = tid & 31, s = tid >> 5;
            ull v = sh_part[l * 9 + s];
#pragma unroll
            for (int k2 = 1; k2 < 8; k2++) fadd2(v, sh_part[((k2 << 5) + l) * 9 + s]);
            float2 vf = unpack2(v);
            int ma = s >> 1, half = s & 1;
            int row  = ma * 16 + (l >> 2) + 8 * half;
            int bcol = (l & 3) * 2;
            sh_gate[row * 10 + bcol]     = vf.x;
            sh_gate[row * 10 + bcol + 1] = vf.y;
        }
        __syncthreads();

        // ---- epilogue + producer-side bf16 packing ----
        float h_new = 0.f;
        if (tid < 128) {
            const float* gr = sh_gate + (4 * jl) * 10 + b8;
            float pi = gr[0]  + gxv.x;
            float pf = gr[10] + gxv.y;
            float pg = gr[20] + gxv.z;
            float po = gr[30] + gxv.w;
            float ig = sigf(pi), fg = sigf(pf), og = sigf(po);
            float gg = tanh_fast(pg);
            c_val = fg * c_val + ig * gg;
            h_new = og * tanh_fast(c_val);
            float hp = __shfl_xor_sync(0xffffffffu, h_new, 1);
            if (!(jl & 1)) {                     // even jl packs (h_j, h_j+1)
                unsigned hi, lo;
                CVT2(h_new, hp, hi, lo);
                int idx = ((t + 1) & 1) * 2048 + (c * 8 + (jl >> 1)) * 8 + b8;
                gHi[idx] = hi; gLo[idx] = lo;
            }
        }

        // ---- half-barrier arrival, then deferred out[] stores ----
        __syncthreads();                      // publish visible CTA-wide
        if (tid == 0) {
            unsigned arrived = atom_add_rel(cntA, 1u) + 1u;
            if (arrived == (unsigned)(t + 1) * (unsigned)NCH)
                st_rel(genOwn, (unsigned)(t + 1));
        }
        if (tid < 128) {
            out[(size_t)t * BH + (size_t)(grp * 8 + b8) * H_SZ + c * 16 + jl] = h_new;
            if (t == T_STEPS - 1 && out_size >= TBH + 2 * BH) {
                out[TBH + (grp * 8 + b8) * H_SZ + c * 16 + jl]      = h_new;  // h_f
                out[TBH + BH + (grp * 8 + b8) * H_SZ + c * 16 + jl] = c_val;  // c_f
            }
        }
        // no trailing __syncthreads: next-iter hazards covered by bar1/bar2 + sync A/B
    }
}

// ---------------- launch ----------------
extern "C" void kernel_launch(void* const* d_in, const int* in_sizes, int n_in,
                              void* d_out, int out_size) {
    const float* input = (const float*)d_in[0];
    const float* h0    = (const float*)d_in[1];
    const float* c0    = (const float*)d_in[2];
    const float* Wih   = (const float*)d_in[3];
    const float* Whh   = (const float*)d_in[4];
    const float* bih   = (const float*)d_in[5];
    const float* bhh   = (const float*)d_in[6];
    float* out = (float*)d_out;

    prep_kernel<<<G4, 128>>>(Wih, Whh, bih, bhh, h0);
    convert_kernel<<<8192 + 512, 256>>>(input);

    dim3 gridG(G4 / 128, MROWS / 128);
    gemm_tc_kernel<<<gridG, 256>>>();

    const int scan_smem = (4096 + 4608 + 640) * (int)sizeof(float);  // 37376 B
    cudaFuncSetAttribute(scan_kernel, cudaFuncAttributeMaxDynamicSharedMemorySize, scan_smem);
    scan_kernel<<<NG * NC, 256, scan_smem>>>(c0, out, out_size);
}